// round 10
// baseline (speedup 1.0000x reference)
#include <cuda_runtime.h>
#include <cuda_fp16.h>
#include <cstdint>

// Problem dims
#define Bb   8
#define Ss   1024
#define Dd   1024
#define Hh   16
#define DKk  64
#define DFFf 4096
#define MR   (Bb * Ss)   // 8192 rows
#define QKVN 3072

// ---------------- scratch (device globals; no allocations allowed) -------------
__device__ float g_x1  [(size_t)MR * Dd];

__device__ __half g_xn_hi [(size_t)MR * Dd];
__device__ __half g_qkv_hi[(size_t)MR * QKVN];
__device__ __half g_at_hi [(size_t)MR * Dd];
__device__ __half g_f1_hi [(size_t)MR * DFFf];
__device__ __half g_wqkv_hi[(size_t)QKVN * Dd];
__device__ __half g_wo_hi[(size_t)Dd * Dd];
__device__ __half g_w1_hi[(size_t)DFFf * Dd];
__device__ __half g_w2_hi[(size_t)Dd * DFFf];
__device__ float g_bqkv[QKVN];

// ---------------- helpers -------------------------------------------------------
__device__ __forceinline__ uint32_t smem_to_u32(const void* p) {
    uint32_t a;
    asm("{ .reg .u64 t; cvta.to.shared.u64 t, %1; cvt.u32.u64 %0, t; }" : "=r"(a) : "l"(p));
    return a;
}
#define SWZ(off) ((off) ^ (((off) >> 3) & 0x70))

#define CP_ASYNC16(dst, src) \
    asm volatile("cp.async.cg.shared.global [%0], [%1], 16;" :: "r"(dst), "l"(src))
#define CP_COMMIT()  asm volatile("cp.async.commit_group;" ::: "memory")
#define CP_WAIT0()   asm volatile("cp.async.wait_group 0;" ::: "memory")
#define CP_WAIT1()   asm volatile("cp.async.wait_group 1;" ::: "memory")

__device__ __forceinline__ void ldsm4(uint32_t& r0, uint32_t& r1, uint32_t& r2, uint32_t& r3,
                                      uint32_t addr) {
    asm volatile("ldmatrix.sync.aligned.m8n8.x4.shared.b16 {%0,%1,%2,%3}, [%4];"
        : "=r"(r0), "=r"(r1), "=r"(r2), "=r"(r3) : "r"(addr));
}
__device__ __forceinline__ void ldsm4t(uint32_t& r0, uint32_t& r1, uint32_t& r2, uint32_t& r3,
                                       uint32_t addr) {
    asm volatile("ldmatrix.sync.aligned.m8n8.x4.trans.shared.b16 {%0,%1,%2,%3}, [%4];"
        : "=r"(r0), "=r"(r1), "=r"(r2), "=r"(r3) : "r"(addr));
}
__device__ __forceinline__ void mma_f16(float* c, const uint32_t* a, const uint32_t* b) {
    asm volatile(
        "mma.sync.aligned.m16n8k16.row.col.f32.f16.f16.f32 "
        "{%0,%1,%2,%3}, {%4,%5,%6,%7}, {%8,%9}, {%0,%1,%2,%3};"
        : "+f"(c[0]), "+f"(c[1]), "+f"(c[2]), "+f"(c[3])
        : "r"(a[0]), "r"(a[1]), "r"(a[2]), "r"(a[3]), "r"(b[0]), "r"(b[1]));
}

__device__ __forceinline__ uint32_t pack_h2(float a, float b) {
    __half ha = __float2half_rn(a), hb = __float2half_rn(b);
    return (uint32_t)__half_as_ushort(ha) | ((uint32_t)__half_as_ushort(hb) << 16);
}

// ---------------- LayerNorm -> fp16 output -------------------------------------
__global__ void __launch_bounds__(256) ln_kernel(
    const float* __restrict__ x, __half* __restrict__ ohi,
    const float* __restrict__ gamma, const float* __restrict__ beta)
{
    const int row = blockIdx.x;
    const float* xr = x + (size_t)row * Dd;
    float s = 0.f, sq = 0.f;
    for (int i = threadIdx.x; i < Dd; i += 256) {
        float v = xr[i]; s += v; sq += v * v;
    }
    #pragma unroll
    for (int o = 16; o > 0; o >>= 1) {
        s  += __shfl_xor_sync(0xffffffffu, s, o);
        sq += __shfl_xor_sync(0xffffffffu, sq, o);
    }
    __shared__ float rs[8], rq[8];
    __shared__ float bmu, brstd;
    const int w = threadIdx.x >> 5, l = threadIdx.x & 31;
    if (l == 0) { rs[w] = s; rq[w] = sq; }
    __syncthreads();
    if (threadIdx.x == 0) {
        float ts = 0.f, tq = 0.f;
        #pragma unroll
        for (int i = 0; i < 8; i++) { ts += rs[i]; tq += rq[i]; }
        float mu  = ts / (float)Dd;
        float var = (tq - (float)Dd * mu * mu) / (float)(Dd - 1);
        bmu = mu; brstd = rsqrtf(var + 1e-5f);
    }
    __syncthreads();
    const float g = gamma[0], be = beta[0];
    const float mu = bmu, rstd = brstd;
    for (int i = threadIdx.x; i < Dd; i += 256)
        ohi[(size_t)row * Dd + i] = __float2half_rn(g * (xr[i] - mu) * rstd + be);
}

// ---------------- fp32 -> fp16 conversion (weights), 1 float4/thread -----------
__global__ void __launch_bounds__(256) conv_h(
    const float* __restrict__ x, __half* __restrict__ hi, int n4)
{
    const int i = blockIdx.x * 256 + threadIdx.x;
    if (i >= n4) return;
    float4 v = ((const float4*)x)[i];
    ((uint2*)hi)[i] = make_uint2(pack_h2(v.x, v.y), pack_h2(v.z, v.w));
}

// ---------------- pack Q/K/V biases into one vector ----------------------------
__global__ void pack_bias(const float* __restrict__ b0, const float* __restrict__ b1,
                          const float* __restrict__ b2, float* __restrict__ dst)
{
    const int i = blockIdx.x * 256 + threadIdx.x;
    if (i < Dd) { dst[i] = b0[i]; dst[Dd + i] = b1[i]; dst[2 * Dd + i] = b2[i]; }
}

// ---------------- fp16 mma GEMM: C = A * W^T -----------------------------------
// 128x128 CTA tile, 256 threads = 8 warps (2M x 4N), warp tile 64x32.
// MODE 1: out fp32 = acc + bias + res
// MODE 2: relu(acc + bias) -> fp16
// MODE 3: (acc + bias)     -> fp16
#define T_AHI 0
#define T_WHI 16384
#define STAGE 32768
#define GEMM_SMEM_DYN 98304   // 3 stages

template<int MODE>
__global__ void __launch_bounds__(256, 2) gemm_mma(
    const __half* __restrict__ Ah, const __half* __restrict__ Wh,
    const float* __restrict__ bias, const float* __restrict__ res,
    float* __restrict__ outF, __half* __restrict__ outHi,
    int K, int N)
{
    extern __shared__ char smem[];
    const uint32_t sbase = smem_to_u32(smem);
    const int tid = threadIdx.x, wid = tid >> 5, lane = tid & 31;
    const int rowBase = blockIdx.y * 128, colBase = blockIdx.x * 128;
    const int warpM = wid & 1, warpN = wid >> 1;     // 2x4 warp grid

    float acc[4][4][4];
    #pragma unroll
    for (int mt = 0; mt < 4; mt++)
        #pragma unroll
        for (int nt = 0; nt < 4; nt++)
            #pragma unroll
            for (int r = 0; r < 4; r++) acc[mt][nt][r] = 0.f;

    const int nch = K >> 6;

    #define PREFETCH(cc, buf) do { \
        const int k0_ = (cc) << 6; \
        const uint32_t sb_ = sbase + (buf) * STAGE; \
        _Pragma("unroll") \
        for (int i_ = 0; i_ < 4; i_++) { \
            const int s_ = tid + 256 * i_; \
            const int row_ = s_ >> 3, c_ = s_ & 7; \
            const uint32_t sw_ = SWZ((uint32_t)(row_ * 128 + c_ * 16)); \
            CP_ASYNC16(sb_ + T_AHI + sw_, Ah + (size_t)(rowBase + row_) * K + k0_ + c_ * 8); \
            CP_ASYNC16(sb_ + T_WHI + sw_, Wh + (size_t)(colBase + row_) * K + k0_ + c_ * 8); \
        } \
    } while (0)

    PREFETCH(0, 0); CP_COMMIT();
    PREFETCH(1, 1); CP_COMMIT();

    int buf = 0;
    for (int c = 0; c < nch; c++) {
        if (c < nch - 1) CP_WAIT1(); else CP_WAIT0();
        __syncthreads();
        if (c + 2 < nch) {
            int nb = buf + 2; if (nb >= 3) nb -= 3;
            PREFETCH(c + 2, nb); CP_COMMIT();
        }
        const uint32_t sb = sbase + buf * STAGE;

        #pragma unroll
        for (int ks = 0; ks < 4; ks++) {
            uint32_t ah[4][4];
            #pragma unroll
            for (int mt = 0; mt < 4; mt++) {
                const int r = warpM * 64 + mt * 16 + (lane & 15);
                const uint32_t off = SWZ((uint32_t)(r * 128 + ks * 32 + ((lane >> 4) << 4)));
                ldsm4(ah[mt][0], ah[mt][1], ah[mt][2], ah[mt][3], sb + T_AHI + off);
            }
            uint32_t bh[4][2];
            #pragma unroll
            for (int ng = 0; ng < 2; ng++) {
                const int r = warpN * 32 + ng * 16 + (lane & 7) + ((lane >> 4) << 3);
                const uint32_t off = SWZ((uint32_t)(r * 128 + ks * 32 + (((lane >> 3) & 1) << 4)));
                uint32_t q0, q1, q2, q3;
                ldsm4(q0, q1, q2, q3, sb + T_WHI + off);
                bh[ng * 2][0] = q0; bh[ng * 2][1] = q1;
                bh[ng * 2 + 1][0] = q2; bh[ng * 2 + 1][1] = q3;
            }
            #pragma unroll
            for (int mt = 0; mt < 4; mt++)
                #pragma unroll
                for (int nt = 0; nt < 4; nt++)
                    mma_f16(acc[mt][nt], ah[mt], bh[nt]);
        }
        buf++; if (buf >= 3) buf = 0;
    }

    // epilogue
    #pragma unroll
    for (int mt = 0; mt < 4; mt++) {
        #pragma unroll
        for (int nt = 0; nt < 4; nt++) {
            const int col = colBase + warpN * 32 + nt * 8 + 2 * (lane & 3);
            const int row0 = rowBase + warpM * 64 + mt * 16 + (lane >> 2);
            const float bx = bias[col], by = bias[col + 1];
            #pragma unroll
            for (int h = 0; h < 2; h++) {
                const int row = row0 + h * 8;
                float v0 = acc[mt][nt][h * 2]     + bx;
                float v1 = acc[mt][nt][h * 2 + 1] + by;
                if (MODE == 2) {
                    v0 = fmaxf(v0, 0.f); v1 = fmaxf(v1, 0.f);
                    ((uint32_t*)outHi)[((size_t)row * N + col) >> 1] = pack_h2(v0, v1);
                } else if (MODE == 3) {
                    ((uint32_t*)outHi)[((size_t)row * N + col) >> 1] = pack_h2(v0, v1);
                } else {
                    const float2 rv = *(const float2*)&res[(size_t)row * N + col];
                    float2 o = { v0 + rv.x, v1 + rv.y };
                    *(float2*)&outF[(size_t)row * N + col] = o;
                }
            }
        }
    }
}

// ---------------- Fused flash attention (fp16 mma) -----------------------------
// Q 16KB + 3 KV stages x 32KB {KH,VH} = 112 KB; 2 CTAs/SM
#define SQH 0
#define KV0 16384
#define KVSTG 32768
#define AKH 0
#define AVH 16384
#define ATT_SMEM_DYN 114688

__global__ void __launch_bounds__(256, 2) attn_kernel(
    const __half* __restrict__ QKVh, __half* __restrict__ Oh)
{
    extern __shared__ char smem[];
    const uint32_t sb = smem_to_u32(smem);
    const int tid = threadIdx.x, wid = tid >> 5, lane = tid & 31;
    const int bh = blockIdx.y, b = bh >> 4, h = bh & 15;
    const int q0 = blockIdx.x * 128;
    const size_t qtok = (size_t)b * Ss + q0;
    const int hcol = h * DKk;
    const int qr = wid * 16;

    #define PREFETCH_KV(kt_, buf_) do { \
        const uint32_t kvb_ = sb + KV0 + (buf_) * KVSTG; \
        _Pragma("unroll") \
        for (int i_ = 0; i_ < 4; i_++) { \
            const int s_ = tid + 256 * i_; \
            const int row_ = s_ >> 3, ch_ = s_ & 7; \
            const uint32_t sw_ = SWZ((uint32_t)(row_ * 128 + ch_ * 16)); \
            const size_t gk_ = ((size_t)b * Ss + (kt_) * 128 + row_) * QKVN + Dd + hcol + ch_ * 8; \
            CP_ASYNC16(kvb_ + AKH + sw_, QKVh + gk_); \
            CP_ASYNC16(kvb_ + AVH + sw_, QKVh + gk_ + Dd); \
        } \
    } while (0)

    #pragma unroll
    for (int i = 0; i < 4; i++) {
        const int s = tid + 256 * i;
        const int row = s >> 3, ch = s & 7;
        const uint32_t sw = SWZ((uint32_t)(row * 128 + ch * 16));
        CP_ASYNC16(sb + SQH + sw, QKVh + (qtok + row) * QKVN + hcol + ch * 8);
    }
    PREFETCH_KV(0, 0); CP_COMMIT();
    PREFETCH_KV(1, 1); CP_COMMIT();

    float accO[8][4];
    #pragma unroll
    for (int nt = 0; nt < 8; nt++)
        #pragma unroll
        for (int r = 0; r < 4; r++) accO[nt][r] = 0.f;
    float mrow[2] = { -1e30f, -1e30f };
    float lrow[2] = { 0.f, 0.f };

    int buf = 0;
    for (int kt = 0; kt < 8; kt++) {
        if (kt < 7) CP_WAIT1(); else CP_WAIT0();
        __syncthreads();
        if (kt + 2 < 8) {
            int nb = buf + 2; if (nb >= 3) nb -= 3;
            PREFETCH_KV(kt + 2, nb); CP_COMMIT();
        }
        const uint32_t kvb = sb + KV0 + buf * KVSTG;

        #pragma unroll
        for (int half = 0; half < 2; half++) {
            // ---- S = Q K^T over 64 keys ----
            float sacc[8][4];
            #pragma unroll
            for (int nt = 0; nt < 8; nt++)
                #pragma unroll
                for (int r = 0; r < 4; r++) sacc[nt][r] = 0.f;

            #pragma unroll
            for (int ks = 0; ks < 4; ks++) {
                uint32_t aqh[4];
                {
                    const int r = qr + (lane & 15);
                    const uint32_t off = SWZ((uint32_t)(r * 128 + ks * 32 + ((lane >> 4) << 4)));
                    ldsm4(aqh[0], aqh[1], aqh[2], aqh[3], sb + SQH + off);
                }
                #pragma unroll
                for (int np = 0; np < 4; np++) {
                    const int r = half * 64 + np * 16 + (lane & 7) + ((lane >> 4) << 3);
                    const uint32_t off = SWZ((uint32_t)(r * 128 + ks * 32 + (((lane >> 3) & 1) << 4)));
                    uint32_t kh0, kh1, kh2, kh3;
                    ldsm4(kh0, kh1, kh2, kh3, kvb + AKH + off);
                    uint32_t bH0[2] = { kh0, kh1 }, bH1[2] = { kh2, kh3 };
                    mma_f16(sacc[np * 2],     aqh, bH0);
                    mma_f16(sacc[np * 2 + 1], aqh, bH1);
                }
            }
            #pragma unroll
            for (int nt = 0; nt < 8; nt++)
                #pragma unroll
                for (int r = 0; r < 4; r++) sacc[nt][r] *= 0.125f;

            // ---- online softmax ----
            float mx0 = -1e30f, mx1 = -1e30f;
            #pragma unroll
            for (int nt = 0; nt < 8; nt++) {
                mx0 = fmaxf(mx0, fmaxf(sacc[nt][0], sacc[nt][1]));
                mx1 = fmaxf(mx1, fmaxf(sacc[nt][2], sacc[nt][3]));
            }
            mx0 = fmaxf(mx0, __shfl_xor_sync(0xffffffffu, mx0, 1));
            mx0 = fmaxf(mx0, __shfl_xor_sync(0xffffffffu, mx0, 2));
            mx1 = fmaxf(mx1, __shfl_xor_sync(0xffffffffu, mx1, 1));
            mx1 = fmaxf(mx1, __shfl_xor_sync(0xffffffffu, mx1, 2));
            const float nm0 = fmaxf(mrow[0], mx0), nm1 = fmaxf(mrow[1], mx1);
            const float al0 = __expf(mrow[0] - nm0), al1 = __expf(mrow[1] - nm1);
            mrow[0] = nm0; mrow[1] = nm1;
            float sum0 = 0.f, sum1 = 0.f;
            #pragma unroll
            for (int nt = 0; nt < 8; nt++) {
                sacc[nt][0] = __expf(sacc[nt][0] - nm0);
                sacc[nt][1] = __expf(sacc[nt][1] - nm0);
                sacc[nt][2] = __expf(sacc[nt][2] - nm1);
                sacc[nt][3] = __expf(sacc[nt][3] - nm1);
                sum0 += sacc[nt][0] + sacc[nt][1];
                sum1 += sacc[nt][2] + sacc[nt][3];
                accO[nt][0] *= al0; accO[nt][1] *= al0;
                accO[nt][2] *= al1; accO[nt][3] *= al1;
            }
            sum0 += __shfl_xor_sync(0xffffffffu, sum0, 1);
            sum0 += __shfl_xor_sync(0xffffffffu, sum0, 2);
            sum1 += __shfl_xor_sync(0xffffffffu, sum1, 1);
            sum1 += __shfl_xor_sync(0xffffffffu, sum1, 2);
            lrow[0] = lrow[0] * al0 + sum0;
            lrow[1] = lrow[1] * al1 + sum1;

            // ---- O += P V ----
            #pragma unroll
            for (int t = 0; t < 4; t++) {
                uint32_t pah[4];
                pah[0] = pack_h2(sacc[2 * t][0],     sacc[2 * t][1]);
                pah[1] = pack_h2(sacc[2 * t][2],     sacc[2 * t][3]);
                pah[2] = pack_h2(sacc[2 * t + 1][0], sacc[2 * t + 1][1]);
                pah[3] = pack_h2(sacc[2 * t + 1][2], sacc[2 * t + 1][3]);
                const int k0 = half * 64 + t * 16;
                #pragma unroll
                for (int np = 0; np < 4; np++) {
                    const int krow = k0 + (lane & 15);
                    const int col = np * 16 + ((lane >> 4) << 3);
                    const uint32_t off = SWZ((uint32_t)(krow * 128 + col * 2));
                    uint32_t vh0, vh1, vh2, vh3;
                    ldsm4t(vh0, vh1, vh2, vh3, kvb + AVH + off);
                    uint32_t bH0[2] = { vh0, vh1 }, bH1[2] = { vh2, vh3 };
                    mma_f16(accO[np * 2],     pah, bH0);
                    mma_f16(accO[np * 2 + 1], pah, bH1);
                }
            }
        }
        buf++; if (buf >= 3) buf = 0;
    }

    // ---- epilogue: O / l -> fp16 gmem (stride Dd) ----
    const float inv0 = 1.f / lrow[0], inv1 = 1.f / lrow[1];
    #pragma unroll
    for (int nt = 0; nt < 8; nt++) {
        const int col = hcol + nt * 8 + 2 * (lane & 3);
        #pragma unroll
        for (int g = 0; g < 2; g++) {
            const size_t tok = qtok + qr + (lane >> 2) + g * 8;
            const float inv = g ? inv1 : inv0;
            ((uint32_t*)Oh)[(tok * Dd + col) >> 1] =
                pack_h2(accO[nt][2 * g] * inv, accO[nt][2 * g + 1] * inv);
        }
    }
}

// ---------------- launch --------------------------------------------------------
extern "C" void kernel_launch(void* const* d_in, const int* in_sizes, int n_in,
                              void* d_out, int out_size)
{
    const float* x   = (const float*)d_in[0];
    const float* wq  = (const float*)d_in[2];
    const float* bq  = (const float*)d_in[3];
    const float* wk  = (const float*)d_in[4];
    const float* bk  = (const float*)d_in[5];
    const float* wv  = (const float*)d_in[6];
    const float* bv  = (const float*)d_in[7];
    const float* wo  = (const float*)d_in[8];
    const float* bo  = (const float*)d_in[9];
    const float* w1  = (const float*)d_in[10];
    const float* b1  = (const float*)d_in[11];
    const float* w2  = (const float*)d_in[12];
    const float* b2  = (const float*)d_in[13];
    const float* g1  = (const float*)d_in[14];
    const float* be1 = (const float*)d_in[15];
    const float* g2  = (const float*)d_in[16];
    const float* be2 = (const float*)d_in[17];
    float* out = (float*)d_out;

    float *x1, *bqkv;
    __half *xnh, *qkvh, *ath, *f1h, *wqkvh, *woh, *w1h, *w2h;
    cudaGetSymbolAddress((void**)&x1,    g_x1);
    cudaGetSymbolAddress((void**)&bqkv,  g_bqkv);
    cudaGetSymbolAddress((void**)&xnh,   g_xn_hi);
    cudaGetSymbolAddress((void**)&qkvh,  g_qkv_hi);
    cudaGetSymbolAddress((void**)&ath,   g_at_hi);
    cudaGetSymbolAddress((void**)&f1h,   g_f1_hi);
    cudaGetSymbolAddress((void**)&wqkvh, g_wqkv_hi);
    cudaGetSymbolAddress((void**)&woh,   g_wo_hi);
    cudaGetSymbolAddress((void**)&w1h,   g_w1_hi);
    cudaGetSymbolAddress((void**)&w2h,   g_w2_hi);

    cudaFuncSetAttribute(gemm_mma<1>, cudaFuncAttributeMaxDynamicSharedMemorySize, GEMM_SMEM_DYN);
    cudaFuncSetAttribute(gemm_mma<2>, cudaFuncAttributeMaxDynamicSharedMemorySize, GEMM_SMEM_DYN);
    cudaFuncSetAttribute(gemm_mma<3>, cudaFuncAttributeMaxDynamicSharedMemorySize, GEMM_SMEM_DYN);
    cudaFuncSetAttribute(attn_kernel, cudaFuncAttributeMaxDynamicSharedMemorySize, ATT_SMEM_DYN);

    // weight conversions (wq/wk/wv packed into one [3072 x 1024] buffer)
    const int nDD = Dd * Dd, nW1 = DFFf * Dd;
    conv_h<<<nDD / 1024, 256>>>(wq, wqkvh,                 nDD / 4);
    conv_h<<<nDD / 1024, 256>>>(wk, wqkvh + (size_t)nDD,   nDD / 4);
    conv_h<<<nDD / 1024, 256>>>(wv, wqkvh + (size_t)2*nDD, nDD / 4);
    conv_h<<<nDD / 1024, 256>>>(wo, woh, nDD / 4);
    conv_h<<<nW1 / 1024, 256>>>(w1, w1h, nW1 / 4);
    conv_h<<<nW1 / 1024, 256>>>(w2, w2h, nW1 / 4);
    pack_bias<<<Dd / 256, 256>>>(bq, bk, bv, bqkv);

    // LN1 -> fp16
    ln_kernel<<<MR, 256>>>(x, xnh, g1, be1);

    // fused QKV projection -> packed fp16 [MR x 3072]
    gemm_mma<3><<<dim3(QKVN/128, MR/128), 256, GEMM_SMEM_DYN>>>(
        xnh, wqkvh, bqkv, nullptr, nullptr, qkvh, Dd, QKVN);

    // fused flash attention -> fp16
    attn_kernel<<<dim3(Ss/128, Bb*Hh), 256, ATT_SMEM_DYN>>>(qkvh, ath);

    // output projection + residual (fp32)
    gemm_mma<1><<<dim3(Dd/128, MR/128), 256, GEMM_SMEM_DYN>>>(
        ath, woh, bo, x, x1, nullptr, Dd, Dd);

    // LN2 -> fp16
    ln_kernel<<<MR, 256>>>(x1, xnh, g2, be2);

    // FFN
    gemm_mma<2><<<dim3(DFFf/128, MR/128), 256, GEMM_SMEM_DYN>>>(
        xnh, w1h, b1, nullptr, nullptr, f1h, Dd, DFFf);
    gemm_mma<1><<<dim3(Dd/128, MR/128), 256, GEMM_SMEM_DYN>>>(
        f1h, w2h, b2, x1, out, nullptr, DFFf, Dd);
}

// round 11
// speedup vs baseline: 1.3487x; 1.3487x over previous
#include <cuda_runtime.h>
#include <cuda_fp16.h>
#include <cstdint>

// Problem dims
#define Bb   8
#define Ss   1024
#define Dd   1024
#define Hh   16
#define DKk  64
#define DFFf 4096
#define MR   (Bb * Ss)   // 8192 rows
#define QKVN 3072

// ---------------- scratch (device globals; no allocations allowed) -------------
__device__ float g_x1  [(size_t)MR * Dd];

__device__ __half g_xn_hi [(size_t)MR * Dd];
__device__ __half g_qkv_hi[(size_t)MR * QKVN];
__device__ __half g_at_hi [(size_t)MR * Dd];
__device__ __half g_f1_hi [(size_t)MR * DFFf];
__device__ __half g_wqkv_hi[(size_t)QKVN * Dd];
__device__ __half g_wo_hi[(size_t)Dd * Dd];
__device__ __half g_w1_hi[(size_t)DFFf * Dd];
__device__ __half g_w2_hi[(size_t)Dd * DFFf];
__device__ float g_bqkv[QKVN];

// ---------------- helpers -------------------------------------------------------
__device__ __forceinline__ uint32_t smem_to_u32(const void* p) {
    uint32_t a;
    asm("{ .reg .u64 t; cvta.to.shared.u64 t, %1; cvt.u32.u64 %0, t; }" : "=r"(a) : "l"(p));
    return a;
}
#define SWZ(off) ((off) ^ (((off) >> 3) & 0x70))

#define CP_ASYNC16(dst, src) \
    asm volatile("cp.async.cg.shared.global [%0], [%1], 16;" :: "r"(dst), "l"(src))
#define CP_COMMIT()  asm volatile("cp.async.commit_group;" ::: "memory")
#define CP_WAIT0()   asm volatile("cp.async.wait_group 0;" ::: "memory")
#define CP_WAIT1()   asm volatile("cp.async.wait_group 1;" ::: "memory")

__device__ __forceinline__ void ldsm4(uint32_t& r0, uint32_t& r1, uint32_t& r2, uint32_t& r3,
                                      uint32_t addr) {
    asm volatile("ldmatrix.sync.aligned.m8n8.x4.shared.b16 {%0,%1,%2,%3}, [%4];"
        : "=r"(r0), "=r"(r1), "=r"(r2), "=r"(r3) : "r"(addr));
}
__device__ __forceinline__ void ldsm4t(uint32_t& r0, uint32_t& r1, uint32_t& r2, uint32_t& r3,
                                       uint32_t addr) {
    asm volatile("ldmatrix.sync.aligned.m8n8.x4.trans.shared.b16 {%0,%1,%2,%3}, [%4];"
        : "=r"(r0), "=r"(r1), "=r"(r2), "=r"(r3) : "r"(addr));
}
__device__ __forceinline__ void mma_f16(float* c, const uint32_t* a, const uint32_t* b) {
    asm volatile(
        "mma.sync.aligned.m16n8k16.row.col.f32.f16.f16.f32 "
        "{%0,%1,%2,%3}, {%4,%5,%6,%7}, {%8,%9}, {%0,%1,%2,%3};"
        : "+f"(c[0]), "+f"(c[1]), "+f"(c[2]), "+f"(c[3])
        : "r"(a[0]), "r"(a[1]), "r"(a[2]), "r"(a[3]), "r"(b[0]), "r"(b[1]));
}

__device__ __forceinline__ uint32_t pack_h2(float a, float b) {
    __half ha = __float2half_rn(a), hb = __float2half_rn(b);
    return (uint32_t)__half_as_ushort(ha) | ((uint32_t)__half_as_ushort(hb) << 16);
}

// ---------------- LayerNorm -> fp16 output -------------------------------------
__global__ void __launch_bounds__(256) ln_kernel(
    const float* __restrict__ x, __half* __restrict__ ohi,
    const float* __restrict__ gamma, const float* __restrict__ beta)
{
    const int row = blockIdx.x;
    const float* xr = x + (size_t)row * Dd;
    float s = 0.f, sq = 0.f;
    for (int i = threadIdx.x; i < Dd; i += 256) {
        float v = xr[i]; s += v; sq += v * v;
    }
    #pragma unroll
    for (int o = 16; o > 0; o >>= 1) {
        s  += __shfl_xor_sync(0xffffffffu, s, o);
        sq += __shfl_xor_sync(0xffffffffu, sq, o);
    }
    __shared__ float rs[8], rq[8];
    __shared__ float bmu, brstd;
    const int w = threadIdx.x >> 5, l = threadIdx.x & 31;
    if (l == 0) { rs[w] = s; rq[w] = sq; }
    __syncthreads();
    if (threadIdx.x == 0) {
        float ts = 0.f, tq = 0.f;
        #pragma unroll
        for (int i = 0; i < 8; i++) { ts += rs[i]; tq += rq[i]; }
        float mu  = ts / (float)Dd;
        float var = (tq - (float)Dd * mu * mu) / (float)(Dd - 1);
        bmu = mu; brstd = rsqrtf(var + 1e-5f);
    }
    __syncthreads();
    const float g = gamma[0], be = beta[0];
    const float mu = bmu, rstd = brstd;
    for (int i = threadIdx.x; i < Dd; i += 256)
        ohi[(size_t)row * Dd + i] = __float2half_rn(g * (xr[i] - mu) * rstd + be);
}

// ---------------- fp32 -> fp16 conversion (weights) ----------------------------
__global__ void __launch_bounds__(256) conv_h(
    const float* __restrict__ x, __half* __restrict__ hi, int n4)
{
    const int base = (blockIdx.x * 256 + threadIdx.x) * 4;
    #pragma unroll
    for (int u = 0; u < 4; u++) {
        const int i = base + u;
        if (i >= n4) return;
        float4 v = ((const float4*)x)[i];
        ((uint2*)hi)[i] = make_uint2(pack_h2(v.x, v.y), pack_h2(v.z, v.w));
    }
}

// ---------------- pack Q/K/V biases into one vector ----------------------------
__global__ void pack_bias(const float* __restrict__ b0, const float* __restrict__ b1,
                          const float* __restrict__ b2, float* __restrict__ dst)
{
    const int i = blockIdx.x * 256 + threadIdx.x;
    if (i < Dd) { dst[i] = b0[i]; dst[Dd + i] = b1[i]; dst[2 * Dd + i] = b2[i]; }
}

// ---------------- fp16 mma GEMM: C = A * W^T -----------------------------------
// 128x128 CTA tile, BK=128 (two 64-col subtiles), 512 threads = 16 warps (4x4),
// warp tile 32x32, 2-stage cp.async pipeline (64KB/stage).
// MODE 1: out fp32 = acc + bias + res
// MODE 2: relu(acc + bias) -> fp16
// MODE 3: (acc + bias)     -> fp16
#define T_A 0
#define T_W 32768
#define STAGE 65536
#define GEMM_SMEM_DYN 131072   // 2 stages

template<int MODE>
__global__ void __launch_bounds__(512) gemm_mma(
    const __half* __restrict__ Ah, const __half* __restrict__ Wh,
    const float* __restrict__ bias, const float* __restrict__ res,
    float* __restrict__ outF, __half* __restrict__ outHi,
    int K, int N)
{
    extern __shared__ char smem[];
    const uint32_t sbase = smem_to_u32(smem);
    const int tid = threadIdx.x, wid = tid >> 5, lane = tid & 31;
    const int rowBase = blockIdx.y * 128, colBase = blockIdx.x * 128;
    const int warpM = wid & 3, warpN = wid >> 2;     // 4x4 warp grid

    float acc[2][4][4];
    #pragma unroll
    for (int mt = 0; mt < 2; mt++)
        #pragma unroll
        for (int nt = 0; nt < 4; nt++)
            #pragma unroll
            for (int r = 0; r < 4; r++) acc[mt][nt][r] = 0.f;

    const int nch = K >> 7;   // BK = 128

    // per chunk: 2 subtiles (64 cols each) per matrix, stored at +0 / +16384
    #define PREFETCH(cc, buf) do { \
        const int k0_ = (cc) << 7; \
        const uint32_t sb_ = sbase + (buf) * STAGE; \
        _Pragma("unroll") \
        for (int i_ = 0; i_ < 4; i_++) { \
            const int s_ = tid + 512 * i_;            /* 0..2047 */ \
            const int sub_ = s_ >> 10;                /* 0..1    */ \
            const int r_ = (s_ >> 3) & 127; \
            const int c_ = s_ & 7; \
            const uint32_t sw_ = SWZ((uint32_t)(r_ * 128 + c_ * 16)) + sub_ * 16384; \
            const int kcol_ = k0_ + sub_ * 64 + c_ * 8; \
            CP_ASYNC16(sb_ + T_A + sw_, Ah + (size_t)(rowBase + r_) * K + kcol_); \
            CP_ASYNC16(sb_ + T_W + sw_, Wh + (size_t)(colBase + r_) * K + kcol_); \
        } \
    } while (0)

    PREFETCH(0, 0); CP_COMMIT();

    for (int c = 0; c < nch; c++) {
        CP_WAIT0();
        __syncthreads();
        if (c + 1 < nch) { PREFETCH(c + 1, (c + 1) & 1); CP_COMMIT(); }
        const uint32_t sb = sbase + (c & 1) * STAGE;

        #pragma unroll
        for (int ks = 0; ks < 8; ks++) {
            const uint32_t subo = (uint32_t)((ks >> 2) * 16384);
            const int ksl = ks & 3;
            uint32_t ah[2][4];
            #pragma unroll
            for (int mt = 0; mt < 2; mt++) {
                const int r = warpM * 32 + mt * 16 + (lane & 15);
                const uint32_t off = subo + SWZ((uint32_t)(r * 128 + ksl * 32 + ((lane >> 4) << 4)));
                ldsm4(ah[mt][0], ah[mt][1], ah[mt][2], ah[mt][3], sb + T_A + off);
            }
            uint32_t bh[4][2];
            #pragma unroll
            for (int ng = 0; ng < 2; ng++) {
                const int r = warpN * 32 + ng * 16 + (lane & 7) + ((lane >> 4) << 3);
                const uint32_t off = subo + SWZ((uint32_t)(r * 128 + ksl * 32 + (((lane >> 3) & 1) << 4)));
                uint32_t q0, q1, q2, q3;
                ldsm4(q0, q1, q2, q3, sb + T_W + off);
                bh[ng * 2][0] = q0; bh[ng * 2][1] = q1;
                bh[ng * 2 + 1][0] = q2; bh[ng * 2 + 1][1] = q3;
            }
            #pragma unroll
            for (int mt = 0; mt < 2; mt++)
                #pragma unroll
                for (int nt = 0; nt < 4; nt++)
                    mma_f16(acc[mt][nt], ah[mt], bh[nt]);
        }
        __syncthreads();
    }

    // epilogue
    #pragma unroll
    for (int mt = 0; mt < 2; mt++) {
        #pragma unroll
        for (int nt = 0; nt < 4; nt++) {
            const int col = colBase + warpN * 32 + nt * 8 + 2 * (lane & 3);
            const int row0 = rowBase + warpM * 32 + mt * 16 + (lane >> 2);
            const float bx = bias[col], by = bias[col + 1];
            #pragma unroll
            for (int h = 0; h < 2; h++) {
                const int row = row0 + h * 8;
                float v0 = acc[mt][nt][h * 2]     + bx;
                float v1 = acc[mt][nt][h * 2 + 1] + by;
                if (MODE == 2) {
                    v0 = fmaxf(v0, 0.f); v1 = fmaxf(v1, 0.f);
                    ((uint32_t*)outHi)[((size_t)row * N + col) >> 1] = pack_h2(v0, v1);
                } else if (MODE == 3) {
                    ((uint32_t*)outHi)[((size_t)row * N + col) >> 1] = pack_h2(v0, v1);
                } else {
                    const float2 rv = *(const float2*)&res[(size_t)row * N + col];
                    float2 o = { v0 + rv.x, v1 + rv.y };
                    *(float2*)&outF[(size_t)row * N + col] = o;
                }
            }
        }
    }
}

// ---------------- Fused flash attention (fp16 mma) -----------------------------
// Q 16KB + 3 KV stages x 32KB {KH,VH} = 112 KB
#define SQH 0
#define KV0 16384
#define KVSTG 32768
#define AKH 0
#define AVH 16384
#define ATT_SMEM_DYN 114688

__global__ void __launch_bounds__(256) attn_kernel(
    const __half* __restrict__ QKVh, __half* __restrict__ Oh)
{
    extern __shared__ char smem[];
    const uint32_t sb = smem_to_u32(smem);
    const int tid = threadIdx.x, wid = tid >> 5, lane = tid & 31;
    const int bh = blockIdx.y, b = bh >> 4, h = bh & 15;
    const int q0 = blockIdx.x * 128;
    const size_t qtok = (size_t)b * Ss + q0;
    const int hcol = h * DKk;
    const int qr = wid * 16;

    #define PREFETCH_KV(kt_, buf_) do { \
        const uint32_t kvb_ = sb + KV0 + (buf_) * KVSTG; \
        _Pragma("unroll") \
        for (int i_ = 0; i_ < 4; i_++) { \
            const int s_ = tid + 256 * i_; \
            const int row_ = s_ >> 3, ch_ = s_ & 7; \
            const uint32_t sw_ = SWZ((uint32_t)(row_ * 128 + ch_ * 16)); \
            const size_t gk_ = ((size_t)b * Ss + (kt_) * 128 + row_) * QKVN + Dd + hcol + ch_ * 8; \
            CP_ASYNC16(kvb_ + AKH + sw_, QKVh + gk_); \
            CP_ASYNC16(kvb_ + AVH + sw_, QKVh + gk_ + Dd); \
        } \
    } while (0)

    #pragma unroll
    for (int i = 0; i < 4; i++) {
        const int s = tid + 256 * i;
        const int row = s >> 3, ch = s & 7;
        const uint32_t sw = SWZ((uint32_t)(row * 128 + ch * 16));
        CP_ASYNC16(sb + SQH + sw, QKVh + (qtok + row) * QKVN + hcol + ch * 8);
    }
    PREFETCH_KV(0, 0); CP_COMMIT();
    PREFETCH_KV(1, 1); CP_COMMIT();

    float accO[8][4];
    #pragma unroll
    for (int nt = 0; nt < 8; nt++)
        #pragma unroll
        for (int r = 0; r < 4; r++) accO[nt][r] = 0.f;
    float mrow[2] = { -1e30f, -1e30f };
    float lrow[2] = { 0.f, 0.f };

    int buf = 0;
    for (int kt = 0; kt < 8; kt++) {
        if (kt < 7) CP_WAIT1(); else CP_WAIT0();
        __syncthreads();
        if (kt + 2 < 8) {
            int nb = buf + 2; if (nb >= 3) nb -= 3;
            PREFETCH_KV(kt + 2, nb); CP_COMMIT();
        }
        const uint32_t kvb = sb + KV0 + buf * KVSTG;

        #pragma unroll
        for (int half = 0; half < 2; half++) {
            // ---- S = Q K^T over 64 keys ----
            float sacc[8][4];
            #pragma unroll
            for (int nt = 0; nt < 8; nt++)
                #pragma unroll
                for (int r = 0; r < 4; r++) sacc[nt][r] = 0.f;

            #pragma unroll
            for (int ks = 0; ks < 4; ks++) {
                uint32_t aqh[4];
                {
                    const int r = qr + (lane & 15);
                    const uint32_t off = SWZ((uint32_t)(r * 128 + ks * 32 + ((lane >> 4) << 4)));
                    ldsm4(aqh[0], aqh[1], aqh[2], aqh[3], sb + SQH + off);
                }
                #pragma unroll
                for (int np = 0; np < 4; np++) {
                    const int r = half * 64 + np * 16 + (lane & 7) + ((lane >> 4) << 3);
                    const uint32_t off = SWZ((uint32_t)(r * 128 + ks * 32 + (((lane >> 3) & 1) << 4)));
                    uint32_t kh0, kh1, kh2, kh3;
                    ldsm4(kh0, kh1, kh2, kh3, kvb + AKH + off);
                    uint32_t bH0[2] = { kh0, kh1 }, bH1[2] = { kh2, kh3 };
                    mma_f16(sacc[np * 2],     aqh, bH0);
                    mma_f16(sacc[np * 2 + 1], aqh, bH1);
                }
            }
            #pragma unroll
            for (int nt = 0; nt < 8; nt++)
                #pragma unroll
                for (int r = 0; r < 4; r++) sacc[nt][r] *= 0.125f;

            // ---- online softmax ----
            float mx0 = -1e30f, mx1 = -1e30f;
            #pragma unroll
            for (int nt = 0; nt < 8; nt++) {
                mx0 = fmaxf(mx0, fmaxf(sacc[nt][0], sacc[nt][1]));
                mx1 = fmaxf(mx1, fmaxf(sacc[nt][2], sacc[nt][3]));
            }
            mx0 = fmaxf(mx0, __shfl_xor_sync(0xffffffffu, mx0, 1));
            mx0 = fmaxf(mx0, __shfl_xor_sync(0xffffffffu, mx0, 2));
            mx1 = fmaxf(mx1, __shfl_xor_sync(0xffffffffu, mx1, 1));
            mx1 = fmaxf(mx1, __shfl_xor_sync(0xffffffffu, mx1, 2));
            const float nm0 = fmaxf(mrow[0], mx0), nm1 = fmaxf(mrow[1], mx1);
            const float al0 = __expf(mrow[0] - nm0), al1 = __expf(mrow[1] - nm1);
            mrow[0] = nm0; mrow[1] = nm1;
            float sum0 = 0.f, sum1 = 0.f;
            #pragma unroll
            for (int nt = 0; nt < 8; nt++) {
                sacc[nt][0] = __expf(sacc[nt][0] - nm0);
                sacc[nt][1] = __expf(sacc[nt][1] - nm0);
                sacc[nt][2] = __expf(sacc[nt][2] - nm1);
                sacc[nt][3] = __expf(sacc[nt][3] - nm1);
                sum0 += sacc[nt][0] + sacc[nt][1];
                sum1 += sacc[nt][2] + sacc[nt][3];
                accO[nt][0] *= al0; accO[nt][1] *= al0;
                accO[nt][2] *= al1; accO[nt][3] *= al1;
            }
            sum0 += __shfl_xor_sync(0xffffffffu, sum0, 1);
            sum0 += __shfl_xor_sync(0xffffffffu, sum0, 2);
            sum1 += __shfl_xor_sync(0xffffffffu, sum1, 1);
            sum1 += __shfl_xor_sync(0xffffffffu, sum1, 2);
            lrow[0] = lrow[0] * al0 + sum0;
            lrow[1] = lrow[1] * al1 + sum1;

            // ---- O += P V ----
            #pragma unroll
            for (int t = 0; t < 4; t++) {
                uint32_t pah[4];
                pah[0] = pack_h2(sacc[2 * t][0],     sacc[2 * t][1]);
                pah[1] = pack_h2(sacc[2 * t][2],     sacc[2 * t][3]);
                pah[2] = pack_h2(sacc[2 * t + 1][0], sacc[2 * t + 1][1]);
                pah[3] = pack_h2(sacc[2 * t + 1][2], sacc[2 * t + 1][3]);
                const int k0 = half * 64 + t * 16;
                #pragma unroll
                for (int np = 0; np < 4; np++) {
                    const int krow = k0 + (lane & 15);
                    const int col = np * 16 + ((lane >> 4) << 3);
                    const uint32_t off = SWZ((uint32_t)(krow * 128 + col * 2));
                    uint32_t vh0, vh1, vh2, vh3;
                    ldsm4t(vh0, vh1, vh2, vh3, kvb + AVH + off);
                    uint32_t bH0[2] = { vh0, vh1 }, bH1[2] = { vh2, vh3 };
                    mma_f16(accO[np * 2],     pah, bH0);
                    mma_f16(accO[np * 2 + 1], pah, bH1);
                }
            }
        }
        buf++; if (buf >= 3) buf = 0;
    }

    // ---- epilogue: O / l -> fp16 gmem (stride Dd) ----
    const float inv0 = 1.f / lrow[0], inv1 = 1.f / lrow[1];
    #pragma unroll
    for (int nt = 0; nt < 8; nt++) {
        const int col = hcol + nt * 8 + 2 * (lane & 3);
        #pragma unroll
        for (int g = 0; g < 2; g++) {
            const size_t tok = qtok + qr + (lane >> 2) + g * 8;
            const float inv = g ? inv1 : inv0;
            ((uint32_t*)Oh)[(tok * Dd + col) >> 1] =
                pack_h2(accO[nt][2 * g] * inv, accO[nt][2 * g + 1] * inv);
        }
    }
}

// ---------------- launch --------------------------------------------------------
extern "C" void kernel_launch(void* const* d_in, const int* in_sizes, int n_in,
                              void* d_out, int out_size)
{
    const float* x   = (const float*)d_in[0];
    const float* wq  = (const float*)d_in[2];
    const float* bq  = (const float*)d_in[3];
    const float* wk  = (const float*)d_in[4];
    const float* bk  = (const float*)d_in[5];
    const float* wv  = (const float*)d_in[6];
    const float* bv  = (const float*)d_in[7];
    const float* wo  = (const float*)d_in[8];
    const float* bo  = (const float*)d_in[9];
    const float* w1  = (const float*)d_in[10];
    const float* b1  = (const float*)d_in[11];
    const float* w2  = (const float*)d_in[12];
    const float* b2  = (const float*)d_in[13];
    const float* g1  = (const float*)d_in[14];
    const float* be1 = (const float*)d_in[15];
    const float* g2  = (const float*)d_in[16];
    const float* be2 = (const float*)d_in[17];
    float* out = (float*)d_out;

    float *x1, *bqkv;
    __half *xnh, *qkvh, *ath, *f1h, *wqkvh, *woh, *w1h, *w2h;
    cudaGetSymbolAddress((void**)&x1,    g_x1);
    cudaGetSymbolAddress((void**)&bqkv,  g_bqkv);
    cudaGetSymbolAddress((void**)&xnh,   g_xn_hi);
    cudaGetSymbolAddress((void**)&qkvh,  g_qkv_hi);
    cudaGetSymbolAddress((void**)&ath,   g_at_hi);
    cudaGetSymbolAddress((void**)&f1h,   g_f1_hi);
    cudaGetSymbolAddress((void**)&wqkvh, g_wqkv_hi);
    cudaGetSymbolAddress((void**)&woh,   g_wo_hi);
    cudaGetSymbolAddress((void**)&w1h,   g_w1_hi);
    cudaGetSymbolAddress((void**)&w2h,   g_w2_hi);

    cudaFuncSetAttribute(gemm_mma<1>, cudaFuncAttributeMaxDynamicSharedMemorySize, GEMM_SMEM_DYN);
    cudaFuncSetAttribute(gemm_mma<2>, cudaFuncAttributeMaxDynamicSharedMemorySize, GEMM_SMEM_DYN);
    cudaFuncSetAttribute(gemm_mma<3>, cudaFuncAttributeMaxDynamicSharedMemorySize, GEMM_SMEM_DYN);
    cudaFuncSetAttribute(attn_kernel, cudaFuncAttributeMaxDynamicSharedMemorySize, ATT_SMEM_DYN);

    // weight conversions (wq/wk/wv packed into one [3072 x 1024] buffer)
    const int nDD = Dd * Dd, nW1 = DFFf * Dd;
    conv_h<<<nDD / 4096, 256>>>(wq, wqkvh,                 nDD / 4);
    conv_h<<<nDD / 4096, 256>>>(wk, wqkvh + (size_t)nDD,   nDD / 4);
    conv_h<<<nDD / 4096, 256>>>(wv, wqkvh + (size_t)2*nDD, nDD / 4);
    conv_h<<<nDD / 4096, 256>>>(wo, woh, nDD / 4);
    conv_h<<<nW1 / 4096, 256>>>(w1, w1h, nW1 / 4);
    conv_h<<<nW1 / 4096, 256>>>(w2, w2h, nW1 / 4);
    pack_bias<<<Dd / 256, 256>>>(bq, bk, bv, bqkv);

    // LN1 -> fp16
    ln_kernel<<<MR, 256>>>(x, xnh, g1, be1);

    // fused QKV projection -> packed fp16 [MR x 3072]
    gemm_mma<3><<<dim3(QKVN/128, MR/128), 512, GEMM_SMEM_DYN>>>(
        xnh, wqkvh, bqkv, nullptr, nullptr, qkvh, Dd, QKVN);

    // fused flash attention -> fp16
    attn_kernel<<<dim3(Ss/128, Bb*Hh), 256, ATT_SMEM_DYN>>>(qkvh, ath);

    // output projection + residual (fp32)
    gemm_mma<1><<<dim3(Dd/128, MR/128), 512, GEMM_SMEM_DYN>>>(
        ath, woh, bo, x, x1, nullptr, Dd, Dd);

    // LN2 -> fp16
    ln_kernel<<<MR, 256>>>(x1, xnh, g2, be2);

    // FFN
    gemm_mma<2><<<dim3(DFFf/128, MR/128), 512, GEMM_SMEM_DYN>>>(
        xnh, w1h, b1, nullptr, nullptr, f1h, Dd, DFFf);
    gemm_mma<1><<<dim3(Dd/128, MR/128), 512, GEMM_SMEM_DYN>>>(
        f1h, w2h, b2, x1, out, nullptr, DFFf, Dd);
}

// round 13
// speedup vs baseline: 1.3878x; 1.0290x over previous
#include <cuda_runtime.h>
#include <cuda_fp16.h>
#include <cstdint>

// Problem dims
#define Bb   8
#define Ss   1024
#define Dd   1024
#define Hh   16
#define DKk  64
#define DFFf 4096
#define MR   (Bb * Ss)   // 8192 rows
#define QKVN 3072

// ---------------- scratch (device globals; no allocations allowed) -------------
__device__ float g_x1  [(size_t)MR * Dd];

__device__ __half g_xn_hi [(size_t)MR * Dd];
__device__ __half g_qkv_hi[(size_t)MR * QKVN];
__device__ __half g_at_hi [(size_t)MR * Dd];
__device__ __half g_f1_hi [(size_t)MR * DFFf];
__device__ __half g_wqkv_hi[(size_t)QKVN * Dd];
__device__ __half g_wo_hi[(size_t)Dd * Dd];
__device__ __half g_w1_hi[(size_t)DFFf * Dd];
__device__ __half g_w2_hi[(size_t)Dd * DFFf];
__device__ float g_bqkv[QKVN];

// ---------------- helpers -------------------------------------------------------
__device__ __forceinline__ uint32_t smem_to_u32(const void* p) {
    uint32_t a;
    asm("{ .reg .u64 t; cvta.to.shared.u64 t, %1; cvt.u32.u64 %0, t; }" : "=r"(a) : "l"(p));
    return a;
}
#define SWZ(off) ((off) ^ (((off) >> 3) & 0x70))

#define CP_ASYNC16(dst, src) \
    asm volatile("cp.async.cg.shared.global [%0], [%1], 16;" :: "r"(dst), "l"(src))
#define CP_COMMIT()  asm volatile("cp.async.commit_group;" ::: "memory")
#define CP_WAIT0()   asm volatile("cp.async.wait_group 0;" ::: "memory")
#define CP_WAIT1()   asm volatile("cp.async.wait_group 1;" ::: "memory")

__device__ __forceinline__ void ldsm4(uint32_t& r0, uint32_t& r1, uint32_t& r2, uint32_t& r3,
                                      uint32_t addr) {
    asm volatile("ldmatrix.sync.aligned.m8n8.x4.shared.b16 {%0,%1,%2,%3}, [%4];"
        : "=r"(r0), "=r"(r1), "=r"(r2), "=r"(r3) : "r"(addr));
}
__device__ __forceinline__ void ldsm4t(uint32_t& r0, uint32_t& r1, uint32_t& r2, uint32_t& r3,
                                       uint32_t addr) {
    asm volatile("ldmatrix.sync.aligned.m8n8.x4.trans.shared.b16 {%0,%1,%2,%3}, [%4];"
        : "=r"(r0), "=r"(r1), "=r"(r2), "=r"(r3) : "r"(addr));
}
__device__ __forceinline__ void mma_f16(float* c, const uint32_t* a, const uint32_t* b) {
    asm volatile(
        "mma.sync.aligned.m16n8k16.row.col.f32.f16.f16.f32 "
        "{%0,%1,%2,%3}, {%4,%5,%6,%7}, {%8,%9}, {%0,%1,%2,%3};"
        : "+f"(c[0]), "+f"(c[1]), "+f"(c[2]), "+f"(c[3])
        : "r"(a[0]), "r"(a[1]), "r"(a[2]), "r"(a[3]), "r"(b[0]), "r"(b[1]));
}

__device__ __forceinline__ uint32_t pack_h2(float a, float b) {
    __half ha = __float2half_rn(a), hb = __float2half_rn(b);
    return (uint32_t)__half_as_ushort(ha) | ((uint32_t)__half_as_ushort(hb) << 16);
}

// ---------------- LayerNorm -> fp16, one pass, float4 --------------------------
__global__ void __launch_bounds__(256) ln_kernel(
    const float* __restrict__ x, __half* __restrict__ ohi,
    const float* __restrict__ gamma, const float* __restrict__ beta)
{
    const int row = blockIdx.x;
    const int t = threadIdx.x;
    const float4 v = ((const float4*)(x + (size_t)row * Dd))[t];
    float s  = v.x + v.y + v.z + v.w;
    float sq = v.x * v.x + v.y * v.y + v.z * v.z + v.w * v.w;
    #pragma unroll
    for (int o = 16; o > 0; o >>= 1) {
        s  += __shfl_xor_sync(0xffffffffu, s, o);
        sq += __shfl_xor_sync(0xffffffffu, sq, o);
    }
    __shared__ float rs[8], rq[8];
    __shared__ float bmu, brstd;
    const int w = t >> 5, l = t & 31;
    if (l == 0) { rs[w] = s; rq[w] = sq; }
    __syncthreads();
    if (t == 0) {
        float ts = 0.f, tq = 0.f;
        #pragma unroll
        for (int i = 0; i < 8; i++) { ts += rs[i]; tq += rq[i]; }
        float mu  = ts / (float)Dd;
        float var = (tq - (float)Dd * mu * mu) / (float)(Dd - 1);
        bmu = mu; brstd = rsqrtf(var + 1e-5f);
    }
    __syncthreads();
    const float g = gamma[0], be = beta[0];
    const float mu = bmu, rstd = brstd;
    const float a = g * rstd;                  // out = a*(x-mu)+be
    const float c = be - a * mu;
    ((uint2*)(ohi + (size_t)row * Dd))[t] =
        make_uint2(pack_h2(fmaf(a, v.x, c), fmaf(a, v.y, c)),
                   pack_h2(fmaf(a, v.z, c), fmaf(a, v.w, c)));
}

// ---------------- fused fp32 -> fp16 conversion of ALL weights -----------------
// Segments (float4 units): wq[0,256K) wk[256K,512K) wv[512K,768K) wo[768K,1M)
//                          w1[1M,2M) w2[2M,3M)
#define SEG (Dd * Dd / 4)   // 256K float4s
__global__ void __launch_bounds__(256) conv_all(
    const float* __restrict__ wq, const float* __restrict__ wk,
    const float* __restrict__ wv, const float* __restrict__ wo,
    const float* __restrict__ w1, const float* __restrict__ w2,
    __half* __restrict__ wqkvh, __half* __restrict__ woh,
    __half* __restrict__ w1h, __half* __restrict__ w2h)
{
    const int gid = blockIdx.x * 256 + threadIdx.x;   // 0 .. 3M-1
    const float* src;
    __half* dst;
    int loc;
    if (gid < 4 * SEG) {
        const int seg = gid >> 18;                    // SEG = 2^18
        loc = gid & (SEG - 1);
        if (seg == 0)      { src = wq; dst = wqkvh; }
        else if (seg == 1) { src = wk; dst = wqkvh + (size_t)Dd * Dd; }
        else if (seg == 2) { src = wv; dst = wqkvh + (size_t)2 * Dd * Dd; }
        else               { src = wo; dst = woh; }
    } else if (gid < 8 * SEG) {
        src = w1; dst = w1h; loc = gid - 4 * SEG;
    } else {
        src = w2; dst = w2h; loc = gid - 8 * SEG;
    }
    const float4 v = ((const float4*)src)[loc];
    ((uint2*)dst)[loc] = make_uint2(pack_h2(v.x, v.y), pack_h2(v.z, v.w));
}

// ---------------- pack Q/K/V biases into one vector ----------------------------
__global__ void pack_bias(const float* __restrict__ b0, const float* __restrict__ b1,
                          const float* __restrict__ b2, float* __restrict__ dst)
{
    const int i = blockIdx.x * 256 + threadIdx.x;
    if (i < Dd) { dst[i] = b0[i]; dst[Dd + i] = b1[i]; dst[2 * Dd + i] = b2[i]; }
}

// ---------------- fp16 mma GEMM: C = A * W^T -----------------------------------
// 128x128 CTA tile, BK=128 (two 64-col subtiles), 512 threads = 16 warps (4x4),
// warp tile 32x32, 2-stage cp.async pipeline (64KB/stage).
// MODE 1: out fp32 = acc + bias + res
// MODE 2: relu(acc + bias) -> fp16
// MODE 3: (acc + bias)     -> fp16
#define T_A 0
#define T_W 32768
#define STAGE 65536
#define GEMM_SMEM_DYN 131072   // 2 stages

template<int MODE>
__global__ void __launch_bounds__(512) gemm_mma(
    const __half* __restrict__ Ah, const __half* __restrict__ Wh,
    const float* __restrict__ bias, const float* __restrict__ res,
    float* __restrict__ outF, __half* __restrict__ outHi,
    int K, int N)
{
    extern __shared__ char smem[];
    const uint32_t sbase = smem_to_u32(smem);
    const int tid = threadIdx.x, wid = tid >> 5, lane = tid & 31;
    const int rowBase = blockIdx.y * 128, colBase = blockIdx.x * 128;
    const int warpM = wid & 3, warpN = wid >> 2;     // 4x4 warp grid

    float acc[2][4][4];
    #pragma unroll
    for (int mt = 0; mt < 2; mt++)
        #pragma unroll
        for (int nt = 0; nt < 4; nt++)
            #pragma unroll
            for (int r = 0; r < 4; r++) acc[mt][nt][r] = 0.f;

    const int nch = K >> 7;   // BK = 128

    #define PREFETCH(cc, buf) do { \
        const int k0_ = (cc) << 7; \
        const uint32_t sb_ = sbase + (buf) * STAGE; \
        _Pragma("unroll") \
        for (int i_ = 0; i_ < 4; i_++) { \
            const int s_ = tid + 512 * i_;            /* 0..2047 */ \
            const int sub_ = s_ >> 10;                /* 0..1    */ \
            const int r_ = (s_ >> 3) & 127; \
            const int c_ = s_ & 7; \
            const uint32_t sw_ = SWZ((uint32_t)(r_ * 128 + c_ * 16)) + sub_ * 16384; \
            const int kcol_ = k0_ + sub_ * 64 + c_ * 8; \
            CP_ASYNC16(sb_ + T_A + sw_, Ah + (size_t)(rowBase + r_) * K + kcol_); \
            CP_ASYNC16(sb_ + T_W + sw_, Wh + (size_t)(colBase + r_) * K + kcol_); \
        } \
    } while (0)

    PREFETCH(0, 0); CP_COMMIT();

    for (int c = 0; c < nch; c++) {
        CP_WAIT0();
        __syncthreads();
        if (c + 1 < nch) { PREFETCH(c + 1, (c + 1) & 1); CP_COMMIT(); }
        const uint32_t sb = sbase + (c & 1) * STAGE;

        #pragma unroll
        for (int ks = 0; ks < 8; ks++) {
            const uint32_t subo = (uint32_t)((ks >> 2) * 16384);
            const int ksl = ks & 3;
            uint32_t ah[2][4];
            #pragma unroll
            for (int mt = 0; mt < 2; mt++) {
                const int r = warpM * 32 + mt * 16 + (lane & 15);
                const uint32_t off = subo + SWZ((uint32_t)(r * 128 + ksl * 32 + ((lane >> 4) << 4)));
                ldsm4(ah[mt][0], ah[mt][1], ah[mt][2], ah[mt][3], sb + T_A + off);
            }
            uint32_t bh[4][2];
            #pragma unroll
            for (int ng = 0; ng < 2; ng++) {
                const int r = warpN * 32 + ng * 16 + (lane & 7) + ((lane >> 4) << 3);
                const uint32_t off = subo + SWZ((uint32_t)(r * 128 + ksl * 32 + (((lane >> 3) & 1) << 4)));
                uint32_t q0, q1, q2, q3;
                ldsm4(q0, q1, q2, q3, sb + T_W + off);
                bh[ng * 2][0] = q0; bh[ng * 2][1] = q1;
                bh[ng * 2 + 1][0] = q2; bh[ng * 2 + 1][1] = q3;
            }
            #pragma unroll
            for (int mt = 0; mt < 2; mt++)
                #pragma unroll
                for (int nt = 0; nt < 4; nt++)
                    mma_f16(acc[mt][nt], ah[mt], bh[nt]);
        }
        __syncthreads();
    }

    // epilogue
    #pragma unroll
    for (int mt = 0; mt < 2; mt++) {
        #pragma unroll
        for (int nt = 0; nt < 4; nt++) {
            const int col = colBase + warpN * 32 + nt * 8 + 2 * (lane & 3);
            const int row0 = rowBase + warpM * 32 + mt * 16 + (lane >> 2);
            const float bx = bias[col], by = bias[col + 1];
            #pragma unroll
            for (int h = 0; h < 2; h++) {
                const int row = row0 + h * 8;
                float v0 = acc[mt][nt][h * 2]     + bx;
                float v1 = acc[mt][nt][h * 2 + 1] + by;
                if (MODE == 2) {
                    v0 = fmaxf(v0, 0.f); v1 = fmaxf(v1, 0.f);
                    ((uint32_t*)outHi)[((size_t)row * N + col) >> 1] = pack_h2(v0, v1);
                } else if (MODE == 3) {
                    ((uint32_t*)outHi)[((size_t)row * N + col) >> 1] = pack_h2(v0, v1);
                } else {
                    const float2 rv = *(const float2*)&res[(size_t)row * N + col];
                    float2 o = { v0 + rv.x, v1 + rv.y };
                    *(float2*)&outF[(size_t)row * N + col] = o;
                }
            }
        }
    }
}

// ---------------- Fused flash attention (fp16 mma) -----------------------------
// Q 16KB + 3 KV stages x 32KB {KH,VH} = 112 KB
#define SQH 0
#define KV0 16384
#define KVSTG 32768
#define AKH 0
#define AVH 16384
#define ATT_SMEM_DYN 114688

__global__ void __launch_bounds__(256) attn_kernel(
    const __half* __restrict__ QKVh, __half* __restrict__ Oh)
{
    extern __shared__ char smem[];
    const uint32_t sb = smem_to_u32(smem);
    const int tid = threadIdx.x, wid = tid >> 5, lane = tid & 31;
    const int bh = blockIdx.y, b = bh >> 4, h = bh & 15;
    const int q0 = blockIdx.x * 128;
    const size_t qtok = (size_t)b * Ss + q0;
    const int hcol = h * DKk;
    const int qr = wid * 16;

    #define PREFETCH_KV(kt_, buf_) do { \
        const uint32_t kvb_ = sb + KV0 + (buf_) * KVSTG; \
        _Pragma("unroll") \
        for (int i_ = 0; i_ < 4; i_++) { \
            const int s_ = tid + 256 * i_; \
            const int row_ = s_ >> 3, ch_ = s_ & 7; \
            const uint32_t sw_ = SWZ((uint32_t)(row_ * 128 + ch_ * 16)); \
            const size_t gk_ = ((size_t)b * Ss + (kt_) * 128 + row_) * QKVN + Dd + hcol + ch_ * 8; \
            CP_ASYNC16(kvb_ + AKH + sw_, QKVh + gk_); \
            CP_ASYNC16(kvb_ + AVH + sw_, QKVh + gk_ + Dd); \
        } \
    } while (0)

    #pragma unroll
    for (int i = 0; i < 4; i++) {
        const int s = tid + 256 * i;
        const int row = s >> 3, ch = s & 7;
        const uint32_t sw = SWZ((uint32_t)(row * 128 + ch * 16));
        CP_ASYNC16(sb + SQH + sw, QKVh + (qtok + row) * QKVN + hcol + ch * 8);
    }
    PREFETCH_KV(0, 0); CP_COMMIT();
    PREFETCH_KV(1, 1); CP_COMMIT();

    float accO[8][4];
    #pragma unroll
    for (int nt = 0; nt < 8; nt++)
        #pragma unroll
        for (int r = 0; r < 4; r++) accO[nt][r] = 0.f;
    float mrow[2] = { -1e30f, -1e30f };
    float lrow[2] = { 0.f, 0.f };

    int buf = 0;
    for (int kt = 0; kt < 8; kt++) {
        if (kt < 7) CP_WAIT1(); else CP_WAIT0();
        __syncthreads();
        if (kt + 2 < 8) {
            int nb = buf + 2; if (nb >= 3) nb -= 3;
            PREFETCH_KV(kt + 2, nb); CP_COMMIT();
        }
        const uint32_t kvb = sb + KV0 + buf * KVSTG;

        #pragma unroll
        for (int half = 0; half < 2; half++) {
            // ---- S = Q K^T over 64 keys ----
            float sacc[8][4];
            #pragma unroll
            for (int nt = 0; nt < 8; nt++)
                #pragma unroll
                for (int r = 0; r < 4; r++) sacc[nt][r] = 0.f;

            #pragma unroll
            for (int ks = 0; ks < 4; ks++) {
                uint32_t aqh[4];
                {
                    const int r = qr + (lane & 15);
                    const uint32_t off = SWZ((uint32_t)(r * 128 + ks * 32 + ((lane >> 4) << 4)));
                    ldsm4(aqh[0], aqh[1], aqh[2], aqh[3], sb + SQH + off);
                }
                #pragma unroll
                for (int np = 0; np < 4; np++) {
                    const int r = half * 64 + np * 16 + (lane & 7) + ((lane >> 4) << 3);
                    const uint32_t off = SWZ((uint32_t)(r * 128 + ks * 32 + (((lane >> 3) & 1) << 4)));
                    uint32_t kh0, kh1, kh2, kh3;
                    ldsm4(kh0, kh1, kh2, kh3, kvb + AKH + off);
                    uint32_t bH0[2] = { kh0, kh1 }, bH1[2] = { kh2, kh3 };
                    mma_f16(sacc[np * 2],     aqh, bH0);
                    mma_f16(sacc[np * 2 + 1], aqh, bH1);
                }
            }
            #pragma unroll
            for (int nt = 0; nt < 8; nt++)
                #pragma unroll
                for (int r = 0; r < 4; r++) sacc[nt][r] *= 0.125f;

            // ---- online softmax ----
            float mx0 = -1e30f, mx1 = -1e30f;
            #pragma unroll
            for (int nt = 0; nt < 8; nt++) {
                mx0 = fmaxf(mx0, fmaxf(sacc[nt][0], sacc[nt][1]));
                mx1 = fmaxf(mx1, fmaxf(sacc[nt][2], sacc[nt][3]));
            }
            mx0 = fmaxf(mx0, __shfl_xor_sync(0xffffffffu, mx0, 1));
            mx0 = fmaxf(mx0, __shfl_xor_sync(0xffffffffu, mx0, 2));
            mx1 = fmaxf(mx1, __shfl_xor_sync(0xffffffffu, mx1, 1));
            mx1 = fmaxf(mx1, __shfl_xor_sync(0xffffffffu, mx1, 2));
            const float nm0 = fmaxf(mrow[0], mx0), nm1 = fmaxf(mrow[1], mx1);
            const float al0 = __expf(mrow[0] - nm0), al1 = __expf(mrow[1] - nm1);
            mrow[0] = nm0; mrow[1] = nm1;
            float sum0 = 0.f, sum1 = 0.f;
            #pragma unroll
            for (int nt = 0; nt < 8; nt++) {
                sacc[nt][0] = __expf(sacc[nt][0] - nm0);
                sacc[nt][1] = __expf(sacc[nt][1] - nm0);
                sacc[nt][2] = __expf(sacc[nt][2] - nm1);
                sacc[nt][3] = __expf(sacc[nt][3] - nm1);
                sum0 += sacc[nt][0] + sacc[nt][1];
                sum1 += sacc[nt][2] + sacc[nt][3];
                accO[nt][0] *= al0; accO[nt][1] *= al0;
                accO[nt][2] *= al1; accO[nt][3] *= al1;
            }
            sum0 += __shfl_xor_sync(0xffffffffu, sum0, 1);
            sum0 += __shfl_xor_sync(0xffffffffu, sum0, 2);
            sum1 += __shfl_xor_sync(0xffffffffu, sum1, 1);
            sum1 += __shfl_xor_sync(0xffffffffu, sum1, 2);
            lrow[0] = lrow[0] * al0 + sum0;
            lrow[1] = lrow[1] * al1 + sum1;

            // ---- O += P V ----
            #pragma unroll
            for (int t = 0; t < 4; t++) {
                uint32_t pah[4];
                pah[0] = pack_h2(sacc[2 * t][0],     sacc[2 * t][1]);
                pah[1] = pack_h2(sacc[2 * t][2],     sacc[2 * t][3]);
                pah[2] = pack_h2(sacc[2 * t + 1][0], sacc[2 * t + 1][1]);
                pah[3] = pack_h2(sacc[2 * t + 1][2], sacc[2 * t + 1][3]);
                const int k0 = half * 64 + t * 16;
                #pragma unroll
                for (int np = 0; np < 4; np++) {
                    const int krow = k0 + (lane & 15);
                    const int col = np * 16 + ((lane >> 4) << 3);
                    const uint32_t off = SWZ((uint32_t)(krow * 128 + col * 2));
                    uint32_t vh0, vh1, vh2, vh3;
                    ldsm4t(vh0, vh1, vh2, vh3, kvb + AVH + off);
                    uint32_t bH0[2] = { vh0, vh1 }, bH1[2] = { vh2, vh3 };
                    mma_f16(accO[np * 2],     pah, bH0);
                    mma_f16(accO[np * 2 + 1], pah, bH1);
                }
            }
        }
        buf++; if (buf >= 3) buf = 0;
    }

    // ---- epilogue: O / l -> fp16 gmem (stride Dd) ----
    const float inv0 = 1.f / lrow[0], inv1 = 1.f / lrow[1];
    #pragma unroll
    for (int nt = 0; nt < 8; nt++) {
        const int col = hcol + nt * 8 + 2 * (lane & 3);
        #pragma unroll
        for (int g = 0; g < 2; g++) {
            const size_t tok = qtok + qr + (lane >> 2) + g * 8;
            const float inv = g ? inv1 : inv0;
            ((uint32_t*)Oh)[(tok * Dd + col) >> 1] =
                pack_h2(accO[nt][2 * g] * inv, accO[nt][2 * g + 1] * inv);
        }
    }
}

// ---------------- launch --------------------------------------------------------
extern "C" void kernel_launch(void* const* d_in, const int* in_sizes, int n_in,
                              void* d_out, int out_size)
{
    const float* x   = (const float*)d_in[0];
    const float* wq  = (const float*)d_in[2];
    const float* bq  = (const float*)d_in[3];
    const float* wk  = (const float*)d_in[4];
    const float* bk  = (const float*)d_in[5];
    const float* wv  = (const float*)d_in[6];
    const float* bv  = (const float*)d_in[7];
    const float* wo  = (const float*)d_in[8];
    const float* bo  = (const float*)d_in[9];
    const float* w1  = (const float*)d_in[10];
    const float* b1  = (const float*)d_in[11];
    const float* w2  = (const float*)d_in[12];
    const float* b2  = (const float*)d_in[13];
    const float* g1  = (const float*)d_in[14];
    const float* be1 = (const float*)d_in[15];
    const float* g2  = (const float*)d_in[16];
    const float* be2 = (const float*)d_in[17];
    float* out = (float*)d_out;

    float *x1, *bqkv;
    __half *xnh, *qkvh, *ath, *f1h, *wqkvh, *woh, *w1h, *w2h;
    cudaGetSymbolAddress((void**)&x1,    g_x1);
    cudaGetSymbolAddress((void**)&bqkv,  g_bqkv);
    cudaGetSymbolAddress((void**)&xnh,   g_xn_hi);
    cudaGetSymbolAddress((void**)&qkvh,  g_qkv_hi);
    cudaGetSymbolAddress((void**)&ath,   g_at_hi);
    cudaGetSymbolAddress((void**)&f1h,   g_f1_hi);
    cudaGetSymbolAddress((void**)&wqkvh, g_wqkv_hi);
    cudaGetSymbolAddress((void**)&woh,   g_wo_hi);
    cudaGetSymbolAddress((void**)&w1h,   g_w1_hi);
    cudaGetSymbolAddress((void**)&w2h,   g_w2_hi);

    cudaFuncSetAttribute(gemm_mma<1>, cudaFuncAttributeMaxDynamicSharedMemorySize, GEMM_SMEM_DYN);
    cudaFuncSetAttribute(gemm_mma<2>, cudaFuncAttributeMaxDynamicSharedMemorySize, GEMM_SMEM_DYN);
    cudaFuncSetAttribute(gemm_mma<3>, cudaFuncAttributeMaxDynamicSharedMemorySize, GEMM_SMEM_DYN);
    cudaFuncSetAttribute(attn_kernel, cudaFuncAttributeMaxDynamicSharedMemorySize, ATT_SMEM_DYN);

    // all weight conversions in one launch (12M floats = 3M float4s)
    conv_all<<<(12 * SEG) / 256, 256>>>(wq, wk, wv, wo, w1, w2, wqkvh, woh, w1h, w2h);
    pack_bias<<<Dd / 256, 256>>>(bq, bk, bv, bqkv);

    // LN1 -> fp16
    ln_kernel<<<MR, 256>>>(x, xnh, g1, be1);

    // fused QKV projection -> packed fp16 [MR x 3072]
    gemm_mma<3><<<dim3(QKVN/128, MR/128), 512, GEMM_SMEM_DYN>>>(
        xnh, wqkvh, bqkv, nullptr, nullptr, qkvh, Dd, QKVN);

    // fused flash attention -> fp16
    attn_kernel<<<dim3(Ss/128, Bb*Hh), 256, ATT_SMEM_DYN>>>(qkvh, ath);

    // output projection + residual (fp32)
    gemm_mma<1><<<dim3(Dd/128, MR/128), 512, GEMM_SMEM_DYN>>>(
        ath, woh, bo, x, x1, nullptr, Dd, Dd);

    // LN2 -> fp16
    ln_kernel<<<MR, 256>>>(x1, xnh, g2, be2);

    // FFN
    gemm_mma<2><<<dim3(DFFf/128, MR/128), 512, GEMM_SMEM_DYN>>>(
        xnh, w1h, b1, nullptr, nullptr, f1h, Dd, DFFf);
    gemm_mma<1><<<dim3(Dd/128, MR/128), 512, GEMM_SMEM_DYN>>>(
        f1h, w2h, b2, x1, out, nullptr, DFFf, Dd);
}

// round 14
// speedup vs baseline: 1.5169x; 1.0930x over previous
#include <cuda_runtime.h>
#include <cuda_fp16.h>
#include <cstdint>

// Problem dims
#define Bb   8
#define Ss   1024
#define Dd   1024
#define Hh   16
#define DKk  64
#define DFFf 4096
#define MR   (Bb * Ss)   // 8192 rows
#define QKVN 3072

// ---------------- scratch (device globals; no allocations allowed) -------------
__device__ float g_x1  [(size_t)MR * Dd];

__device__ __half g_xn_hi [(size_t)MR * Dd];
__device__ __half g_qkv_hi[(size_t)MR * QKVN];
__device__ __half g_at_hi [(size_t)MR * Dd];
__device__ __half g_f1_hi [(size_t)MR * DFFf];
__device__ __half g_wqkv_hi[(size_t)QKVN * Dd];
__device__ __half g_wo_hi[(size_t)Dd * Dd];
__device__ __half g_w1_hi[(size_t)DFFf * Dd];
__device__ __half g_w2_hi[(size_t)Dd * DFFf];
__device__ float g_bqkv[QKVN];

// ---------------- helpers -------------------------------------------------------
__device__ __forceinline__ uint32_t smem_to_u32(const void* p) {
    uint32_t a;
    asm("{ .reg .u64 t; cvta.to.shared.u64 t, %1; cvt.u32.u64 %0, t; }" : "=r"(a) : "l"(p));
    return a;
}
#define SWZ(off) ((off) ^ (((off) >> 3) & 0x70))

#define CP_ASYNC16(dst, src) \
    asm volatile("cp.async.cg.shared.global [%0], [%1], 16;" :: "r"(dst), "l"(src))
#define CP_COMMIT()  asm volatile("cp.async.commit_group;" ::: "memory")
#define CP_WAIT0()   asm volatile("cp.async.wait_group 0;" ::: "memory")
#define CP_WAIT1()   asm volatile("cp.async.wait_group 1;" ::: "memory")

__device__ __forceinline__ void ldsm4(uint32_t& r0, uint32_t& r1, uint32_t& r2, uint32_t& r3,
                                      uint32_t addr) {
    asm volatile("ldmatrix.sync.aligned.m8n8.x4.shared.b16 {%0,%1,%2,%3}, [%4];"
        : "=r"(r0), "=r"(r1), "=r"(r2), "=r"(r3) : "r"(addr));
}
__device__ __forceinline__ void ldsm4t(uint32_t& r0, uint32_t& r1, uint32_t& r2, uint32_t& r3,
                                       uint32_t addr) {
    asm volatile("ldmatrix.sync.aligned.m8n8.x4.trans.shared.b16 {%0,%1,%2,%3}, [%4];"
        : "=r"(r0), "=r"(r1), "=r"(r2), "=r"(r3) : "r"(addr));
}
__device__ __forceinline__ void mma_f16(float* c, const uint32_t* a, const uint32_t* b) {
    asm volatile(
        "mma.sync.aligned.m16n8k16.row.col.f32.f16.f16.f32 "
        "{%0,%1,%2,%3}, {%4,%5,%6,%7}, {%8,%9}, {%0,%1,%2,%3};"
        : "+f"(c[0]), "+f"(c[1]), "+f"(c[2]), "+f"(c[3])
        : "r"(a[0]), "r"(a[1]), "r"(a[2]), "r"(a[3]), "r"(b[0]), "r"(b[1]));
}

__device__ __forceinline__ uint32_t pack_h2(float a, float b) {
    __half ha = __float2half_rn(a), hb = __float2half_rn(b);
    return (uint32_t)__half_as_ushort(ha) | ((uint32_t)__half_as_ushort(hb) << 16);
}

// ---------------- LayerNorm -> fp16, one pass, float4 --------------------------
__global__ void __launch_bounds__(256) ln_kernel(
    const float* __restrict__ x, __half* __restrict__ ohi,
    const float* __restrict__ gamma, const float* __restrict__ beta)
{
    const int row = blockIdx.x;
    const int t = threadIdx.x;
    const float4 v = ((const float4*)(x + (size_t)row * Dd))[t];
    float s  = v.x + v.y + v.z + v.w;
    float sq = v.x * v.x + v.y * v.y + v.z * v.z + v.w * v.w;
    #pragma unroll
    for (int o = 16; o > 0; o >>= 1) {
        s  += __shfl_xor_sync(0xffffffffu, s, o);
        sq += __shfl_xor_sync(0xffffffffu, sq, o);
    }
    __shared__ float rs[8], rq[8];
    __shared__ float bmu, brstd;
    const int w = t >> 5, l = t & 31;
    if (l == 0) { rs[w] = s; rq[w] = sq; }
    __syncthreads();
    if (t == 0) {
        float ts = 0.f, tq = 0.f;
        #pragma unroll
        for (int i = 0; i < 8; i++) { ts += rs[i]; tq += rq[i]; }
        float mu  = ts / (float)Dd;
        float var = (tq - (float)Dd * mu * mu) / (float)(Dd - 1);
        bmu = mu; brstd = rsqrtf(var + 1e-5f);
    }
    __syncthreads();
    const float g = gamma[0], be = beta[0];
    const float mu = bmu, rstd = brstd;
    const float a = g * rstd;
    const float c = be - a * mu;
    ((uint2*)(ohi + (size_t)row * Dd))[t] =
        make_uint2(pack_h2(fmaf(a, v.x, c), fmaf(a, v.y, c)),
                   pack_h2(fmaf(a, v.z, c), fmaf(a, v.w, c)));
}

// ---------------- fused fp32 -> fp16 conversion of ALL weights -----------------
#define SEG (Dd * Dd / 4)   // 256K float4s
__global__ void __launch_bounds__(256) conv_all(
    const float* __restrict__ wq, const float* __restrict__ wk,
    const float* __restrict__ wv, const float* __restrict__ wo,
    const float* __restrict__ w1, const float* __restrict__ w2,
    __half* __restrict__ wqkvh, __half* __restrict__ woh,
    __half* __restrict__ w1h, __half* __restrict__ w2h)
{
    const int gid = blockIdx.x * 256 + threadIdx.x;
    const float* src;
    __half* dst;
    int loc;
    if (gid < 4 * SEG) {
        const int seg = gid >> 18;
        loc = gid & (SEG - 1);
        if (seg == 0)      { src = wq; dst = wqkvh; }
        else if (seg == 1) { src = wk; dst = wqkvh + (size_t)Dd * Dd; }
        else if (seg == 2) { src = wv; dst = wqkvh + (size_t)2 * Dd * Dd; }
        else               { src = wo; dst = woh; }
    } else if (gid < 8 * SEG) {
        src = w1; dst = w1h; loc = gid - 4 * SEG;
    } else {
        src = w2; dst = w2h; loc = gid - 8 * SEG;
    }
    const float4 v = ((const float4*)src)[loc];
    ((uint2*)dst)[loc] = make_uint2(pack_h2(v.x, v.y), pack_h2(v.z, v.w));
}

// ---------------- pack Q/K/V biases into one vector ----------------------------
__global__ void pack_bias(const float* __restrict__ b0, const float* __restrict__ b1,
                          const float* __restrict__ b2, float* __restrict__ dst)
{
    const int i = blockIdx.x * 256 + threadIdx.x;
    if (i < Dd) { dst[i] = b0[i]; dst[Dd + i] = b1[i]; dst[2 * Dd + i] = b2[i]; }
}

// ---------------- fp16 mma GEMM: C = A * W^T -----------------------------------
// CTA tile 128x256, BK=128. 512 threads = 16 warps (4M x 4N), warp tile 32x64.
// 2-stage cp.async pipeline, 96KB/stage (A 32KB + W 64KB).
// MODE 1: out fp32 = acc + bias + res
// MODE 2: relu(acc + bias) -> fp16
// MODE 3: (acc + bias)     -> fp16
#define T_A 0
#define T_W 32768
#define STAGE 98304
#define GEMM_SMEM_DYN 196608   // 2 stages

template<int MODE>
__global__ void __launch_bounds__(512) gemm_mma(
    const __half* __restrict__ Ah, const __half* __restrict__ Wh,
    const float* __restrict__ bias, const float* __restrict__ res,
    float* __restrict__ outF, __half* __restrict__ outHi,
    int K, int N)
{
    extern __shared__ char smem[];
    const uint32_t sbase = smem_to_u32(smem);
    const int tid = threadIdx.x, wid = tid >> 5, lane = tid & 31;
    const int rowBase = blockIdx.y * 128, colBase = blockIdx.x * 256;
    const int warpM = wid & 3, warpN = wid >> 2;     // 4x4 warp grid

    float acc[2][8][4];
    #pragma unroll
    for (int mt = 0; mt < 2; mt++)
        #pragma unroll
        for (int nt = 0; nt < 8; nt++)
            #pragma unroll
            for (int r = 0; r < 4; r++) acc[mt][nt][r] = 0.f;

    const int nch = K >> 7;   // BK = 128

    // A: 128x128 halves = 2048 16B chunks (2 subtiles of 64 cols @ +0/+16384)
    // W: 256x128 halves = 4096 16B chunks (2 subtiles of 64 cols @ +0/+32768)
    #define PREFETCH(cc, buf) do { \
        const int k0_ = (cc) << 7; \
        const uint32_t sb_ = sbase + (buf) * STAGE; \
        _Pragma("unroll") \
        for (int i_ = 0; i_ < 4; i_++) { \
            const int s_ = tid + 512 * i_; \
            const int sub_ = s_ >> 10; \
            const int r_ = (s_ >> 3) & 127; \
            const int c_ = s_ & 7; \
            const uint32_t sw_ = SWZ((uint32_t)(r_ * 128 + c_ * 16)) + sub_ * 16384; \
            CP_ASYNC16(sb_ + T_A + sw_, Ah + (size_t)(rowBase + r_) * K + k0_ + sub_ * 64 + c_ * 8); \
        } \
        _Pragma("unroll") \
        for (int i_ = 0; i_ < 8; i_++) { \
            const int s_ = tid + 512 * i_; \
            const int sub_ = s_ >> 11; \
            const int r_ = (s_ >> 3) & 255; \
            const int c_ = s_ & 7; \
            const uint32_t sw_ = SWZ((uint32_t)(r_ * 128 + c_ * 16)) + sub_ * 32768; \
            CP_ASYNC16(sb_ + T_W + sw_, Wh + (size_t)(colBase + r_) * K + k0_ + sub_ * 64 + c_ * 8); \
        } \
    } while (0)

    PREFETCH(0, 0); CP_COMMIT();

    for (int c = 0; c < nch; c++) {
        CP_WAIT0();
        __syncthreads();
        if (c + 1 < nch) { PREFETCH(c + 1, (c + 1) & 1); CP_COMMIT(); }
        const uint32_t sb = sbase + (c & 1) * STAGE;

        #pragma unroll
        for (int ks = 0; ks < 8; ks++) {
            const uint32_t suboA = (uint32_t)((ks >> 2) * 16384);
            const uint32_t suboW = (uint32_t)((ks >> 2) * 32768);
            const int ksl = ks & 3;
            uint32_t ah[2][4];
            #pragma unroll
            for (int mt = 0; mt < 2; mt++) {
                const int r = warpM * 32 + mt * 16 + (lane & 15);
                const uint32_t off = suboA + SWZ((uint32_t)(r * 128 + ksl * 32 + ((lane >> 4) << 4)));
                ldsm4(ah[mt][0], ah[mt][1], ah[mt][2], ah[mt][3], sb + T_A + off);
            }
            uint32_t bh[8][2];
            #pragma unroll
            for (int ng = 0; ng < 4; ng++) {
                const int r = warpN * 64 + ng * 16 + (lane & 7) + ((lane >> 4) << 3);
                const uint32_t off = suboW + SWZ((uint32_t)(r * 128 + ksl * 32 + (((lane >> 3) & 1) << 4)));
                uint32_t q0, q1, q2, q3;
                ldsm4(q0, q1, q2, q3, sb + T_W + off);
                bh[ng * 2][0] = q0; bh[ng * 2][1] = q1;
                bh[ng * 2 + 1][0] = q2; bh[ng * 2 + 1][1] = q3;
            }
            #pragma unroll
            for (int mt = 0; mt < 2; mt++)
                #pragma unroll
                for (int nt = 0; nt < 8; nt++)
                    mma_f16(acc[mt][nt], ah[mt], bh[nt]);
        }
        __syncthreads();
    }

    // epilogue
    #pragma unroll
    for (int mt = 0; mt < 2; mt++) {
        #pragma unroll
        for (int nt = 0; nt < 8; nt++) {
            const int col = colBase + warpN * 64 + nt * 8 + 2 * (lane & 3);
            const int row0 = rowBase + warpM * 32 + mt * 16 + (lane >> 2);
            const float bx = bias[col], by = bias[col + 1];
            #pragma unroll
            for (int h = 0; h < 2; h++) {
                const int row = row0 + h * 8;
                float v0 = acc[mt][nt][h * 2]     + bx;
                float v1 = acc[mt][nt][h * 2 + 1] + by;
                if (MODE == 2) {
                    v0 = fmaxf(v0, 0.f); v1 = fmaxf(v1, 0.f);
                    ((uint32_t*)outHi)[((size_t)row * N + col) >> 1] = pack_h2(v0, v1);
                } else if (MODE == 3) {
                    ((uint32_t*)outHi)[((size_t)row * N + col) >> 1] = pack_h2(v0, v1);
                } else {
                    const float2 rv = *(const float2*)&res[(size_t)row * N + col];
                    float2 o = { v0 + rv.x, v1 + rv.y };
                    *(float2*)&outF[(size_t)row * N + col] = o;
                }
            }
        }
    }
}

// ---------------- Fused flash attention (fp16 mma) -----------------------------
// Q 16KB + 3 KV stages x 32KB {KH,VH} = 112 KB
#define SQH 0
#define KV0 16384
#define KVSTG 32768
#define AKH 0
#define AVH 16384
#define ATT_SMEM_DYN 114688

__global__ void __launch_bounds__(256) attn_kernel(
    const __half* __restrict__ QKVh, __half* __restrict__ Oh)
{
    extern __shared__ char smem[];
    const uint32_t sb = smem_to_u32(smem);
    const int tid = threadIdx.x, wid = tid >> 5, lane = tid & 31;
    const int bh = blockIdx.y, b = bh >> 4, h = bh & 15;
    const int q0 = blockIdx.x * 128;
    const size_t qtok = (size_t)b * Ss + q0;
    const int hcol = h * DKk;
    const int qr = wid * 16;

    #define PREFETCH_KV(kt_, buf_) do { \
        const uint32_t kvb_ = sb + KV0 + (buf_) * KVSTG; \
        _Pragma("unroll") \
        for (int i_ = 0; i_ < 4; i_++) { \
            const int s_ = tid + 256 * i_; \
            const int row_ = s_ >> 3, ch_ = s_ & 7; \
            const uint32_t sw_ = SWZ((uint32_t)(row_ * 128 + ch_ * 16)); \
            const size_t gk_ = ((size_t)b * Ss + (kt_) * 128 + row_) * QKVN + Dd + hcol + ch_ * 8; \
            CP_ASYNC16(kvb_ + AKH + sw_, QKVh + gk_); \
            CP_ASYNC16(kvb_ + AVH + sw_, QKVh + gk_ + Dd); \
        } \
    } while (0)

    #pragma unroll
    for (int i = 0; i < 4; i++) {
        const int s = tid + 256 * i;
        const int row = s >> 3, ch = s & 7;
        const uint32_t sw = SWZ((uint32_t)(row * 128 + ch * 16));
        CP_ASYNC16(sb + SQH + sw, QKVh + (qtok + row) * QKVN + hcol + ch * 8);
    }
    PREFETCH_KV(0, 0); CP_COMMIT();
    PREFETCH_KV(1, 1); CP_COMMIT();

    float accO[8][4];
    #pragma unroll
    for (int nt = 0; nt < 8; nt++)
        #pragma unroll
        for (int r = 0; r < 4; r++) accO[nt][r] = 0.f;
    float mrow[2] = { -1e30f, -1e30f };
    float lrow[2] = { 0.f, 0.f };

    int buf = 0;
    for (int kt = 0; kt < 8; kt++) {
        if (kt < 7) CP_WAIT1(); else CP_WAIT0();
        __syncthreads();
        if (kt + 2 < 8) {
            int nb = buf + 2; if (nb >= 3) nb -= 3;
            PREFETCH_KV(kt + 2, nb); CP_COMMIT();
        }
        const uint32_t kvb = sb + KV0 + buf * KVSTG;

        #pragma unroll
        for (int half = 0; half < 2; half++) {
            // ---- S = Q K^T over 64 keys ----
            float sacc[8][4];
            #pragma unroll
            for (int nt = 0; nt < 8; nt++)
                #pragma unroll
                for (int r = 0; r < 4; r++) sacc[nt][r] = 0.f;

            #pragma unroll
            for (int ks = 0; ks < 4; ks++) {
                uint32_t aqh[4];
                {
                    const int r = qr + (lane & 15);
                    const uint32_t off = SWZ((uint32_t)(r * 128 + ks * 32 + ((lane >> 4) << 4)));
                    ldsm4(aqh[0], aqh[1], aqh[2], aqh[3], sb + SQH + off);
                }
                #pragma unroll
                for (int np = 0; np < 4; np++) {
                    const int r = half * 64 + np * 16 + (lane & 7) + ((lane >> 4) << 3);
                    const uint32_t off = SWZ((uint32_t)(r * 128 + ks * 32 + (((lane >> 3) & 1) << 4)));
                    uint32_t kh0, kh1, kh2, kh3;
                    ldsm4(kh0, kh1, kh2, kh3, kvb + AKH + off);
                    uint32_t bH0[2] = { kh0, kh1 }, bH1[2] = { kh2, kh3 };
                    mma_f16(sacc[np * 2],     aqh, bH0);
                    mma_f16(sacc[np * 2 + 1], aqh, bH1);
                }
            }
            #pragma unroll
            for (int nt = 0; nt < 8; nt++)
                #pragma unroll
                for (int r = 0; r < 4; r++) sacc[nt][r] *= 0.125f;

            // ---- online softmax ----
            float mx0 = -1e30f, mx1 = -1e30f;
            #pragma unroll
            for (int nt = 0; nt < 8; nt++) {
                mx0 = fmaxf(mx0, fmaxf(sacc[nt][0], sacc[nt][1]));
                mx1 = fmaxf(mx1, fmaxf(sacc[nt][2], sacc[nt][3]));
            }
            mx0 = fmaxf(mx0, __shfl_xor_sync(0xffffffffu, mx0, 1));
            mx0 = fmaxf(mx0, __shfl_xor_sync(0xffffffffu, mx0, 2));
            mx1 = fmaxf(mx1, __shfl_xor_sync(0xffffffffu, mx1, 1));
            mx1 = fmaxf(mx1, __shfl_xor_sync(0xffffffffu, mx1, 2));
            const float nm0 = fmaxf(mrow[0], mx0), nm1 = fmaxf(mrow[1], mx1);
            const float al0 = __expf(mrow[0] - nm0), al1 = __expf(mrow[1] - nm1);
            mrow[0] = nm0; mrow[1] = nm1;
            float sum0 = 0.f, sum1 = 0.f;
            #pragma unroll
            for (int nt = 0; nt < 8; nt++) {
                sacc[nt][0] = __expf(sacc[nt][0] - nm0);
                sacc[nt][1] = __expf(sacc[nt][1] - nm0);
                sacc[nt][2] = __expf(sacc[nt][2] - nm1);
                sacc[nt][3] = __expf(sacc[nt][3] - nm1);
                sum0 += sacc[nt][0] + sacc[nt][1];
                sum1 += sacc[nt][2] + sacc[nt][3];
                accO[nt][0] *= al0; accO[nt][1] *= al0;
                accO[nt][2] *= al1; accO[nt][3] *= al1;
            }
            sum0 += __shfl_xor_sync(0xffffffffu, sum0, 1);
            sum0 += __shfl_xor_sync(0xffffffffu, sum0, 2);
            sum1 += __shfl_xor_sync(0xffffffffu, sum1, 1);
            sum1 += __shfl_xor_sync(0xffffffffu, sum1, 2);
            lrow[0] = lrow[0] * al0 + sum0;
            lrow[1] = lrow[1] * al1 + sum1;

            // ---- O += P V ----
            #pragma unroll
            for (int t = 0; t < 4; t++) {
                uint32_t pah[4];
                pah[0] = pack_h2(sacc[2 * t][0],     sacc[2 * t][1]);
                pah[1] = pack_h2(sacc[2 * t][2],     sacc[2 * t][3]);
                pah[2] = pack_h2(sacc[2 * t + 1][0], sacc[2 * t + 1][1]);
                pah[3] = pack_h2(sacc[2 * t + 1][2], sacc[2 * t + 1][3]);
                const int k0 = half * 64 + t * 16;
                #pragma unroll
                for (int np = 0; np < 4; np++) {
                    const int krow = k0 + (lane & 15);
                    const int col = np * 16 + ((lane >> 4) << 3);
                    const uint32_t off = SWZ((uint32_t)(krow * 128 + col * 2));
                    uint32_t vh0, vh1, vh2, vh3;
                    ldsm4t(vh0, vh1, vh2, vh3, kvb + AVH + off);
                    uint32_t bH0[2] = { vh0, vh1 }, bH1[2] = { vh2, vh3 };
                    mma_f16(accO[np * 2],     pah, bH0);
                    mma_f16(accO[np * 2 + 1], pah, bH1);
                }
            }
        }
        buf++; if (buf >= 3) buf = 0;
    }

    // ---- epilogue: O / l -> fp16 gmem (stride Dd) ----
    const float inv0 = 1.f / lrow[0], inv1 = 1.f / lrow[1];
    #pragma unroll
    for (int nt = 0; nt < 8; nt++) {
        const int col = hcol + nt * 8 + 2 * (lane & 3);
        #pragma unroll
        for (int g = 0; g < 2; g++) {
            const size_t tok = qtok + qr + (lane >> 2) + g * 8;
            const float inv = g ? inv1 : inv0;
            ((uint32_t*)Oh)[(tok * Dd + col) >> 1] =
                pack_h2(accO[nt][2 * g] * inv, accO[nt][2 * g + 1] * inv);
        }
    }
}

// ---------------- launch --------------------------------------------------------
extern "C" void kernel_launch(void* const* d_in, const int* in_sizes, int n_in,
                              void* d_out, int out_size)
{
    const float* x   = (const float*)d_in[0];
    const float* wq  = (const float*)d_in[2];
    const float* bq  = (const float*)d_in[3];
    const float* wk  = (const float*)d_in[4];
    const float* bk  = (const float*)d_in[5];
    const float* wv  = (const float*)d_in[6];
    const float* bv  = (const float*)d_in[7];
    const float* wo  = (const float*)d_in[8];
    const float* bo  = (const float*)d_in[9];
    const float* w1  = (const float*)d_in[10];
    const float* b1  = (const float*)d_in[11];
    const float* w2  = (const float*)d_in[12];
    const float* b2  = (const float*)d_in[13];
    const float* g1  = (const float*)d_in[14];
    const float* be1 = (const float*)d_in[15];
    const float* g2  = (const float*)d_in[16];
    const float* be2 = (const float*)d_in[17];
    float* out = (float*)d_out;

    float *x1, *bqkv;
    __half *xnh, *qkvh, *ath, *f1h, *wqkvh, *woh, *w1h, *w2h;
    cudaGetSymbolAddress((void**)&x1,    g_x1);
    cudaGetSymbolAddress((void**)&bqkv,  g_bqkv);
    cudaGetSymbolAddress((void**)&xnh,   g_xn_hi);
    cudaGetSymbolAddress((void**)&qkvh,  g_qkv_hi);
    cudaGetSymbolAddress((void**)&ath,   g_at_hi);
    cudaGetSymbolAddress((void**)&f1h,   g_f1_hi);
    cudaGetSymbolAddress((void**)&wqkvh, g_wqkv_hi);
    cudaGetSymbolAddress((void**)&woh,   g_wo_hi);
    cudaGetSymbolAddress((void**)&w1h,   g_w1_hi);
    cudaGetSymbolAddress((void**)&w2h,   g_w2_hi);

    cudaFuncSetAttribute(gemm_mma<1>, cudaFuncAttributeMaxDynamicSharedMemorySize, GEMM_SMEM_DYN);
    cudaFuncSetAttribute(gemm_mma<2>, cudaFuncAttributeMaxDynamicSharedMemorySize, GEMM_SMEM_DYN);
    cudaFuncSetAttribute(gemm_mma<3>, cudaFuncAttributeMaxDynamicSharedMemorySize, GEMM_SMEM_DYN);
    cudaFuncSetAttribute(attn_kernel, cudaFuncAttributeMaxDynamicSharedMemorySize, ATT_SMEM_DYN);

    // all weight conversions in one launch (12M floats = 3M float4s)
    conv_all<<<(12 * SEG) / 256, 256>>>(wq, wk, wv, wo, w1, w2, wqkvh, woh, w1h, w2h);
    pack_bias<<<Dd / 256, 256>>>(bq, bk, bv, bqkv);

    // LN1 -> fp16
    ln_kernel<<<MR, 256>>>(x, xnh, g1, be1);

    // fused QKV projection -> packed fp16 [MR x 3072]
    gemm_mma<3><<<dim3(QKVN/256, MR/128), 512, GEMM_SMEM_DYN>>>(
        xnh, wqkvh, bqkv, nullptr, nullptr, qkvh, Dd, QKVN);

    // fused flash attention -> fp16
    attn_kernel<<<dim3(Ss/128, Bb*Hh), 256, ATT_SMEM_DYN>>>(qkvh, ath);

    // output projection + residual (fp32)
    gemm_mma<1><<<dim3(Dd/256, MR/128), 512, GEMM_SMEM_DYN>>>(
        ath, woh, bo, x, x1, nullptr, Dd, Dd);

    // LN2 -> fp16
    ln_kernel<<<MR, 256>>>(x1, xnh, g2, be2);

    // FFN
    gemm_mma<2><<<dim3(DFFf/256, MR/128), 512, GEMM_SMEM_DYN>>>(
        xnh, w1h, b1, nullptr, nullptr, f1h, Dd, DFFf);
    gemm_mma<1><<<dim3(Dd/256, MR/128), 512, GEMM_SMEM_DYN>>>(
        f1h, w2h, b2, x1, out, nullptr, DFFf, Dd);
}

// round 15
// speedup vs baseline: 1.5267x; 1.0065x over previous
#include <cuda_runtime.h>
#include <cuda_fp16.h>
#include <cstdint>

// Problem dims
#define Bb   8
#define Ss   1024
#define Dd   1024
#define Hh   16
#define DKk  64
#define DFFf 4096
#define MR   (Bb * Ss)   // 8192 rows
#define QKVN 3072

// ---------------- scratch (device globals; no allocations allowed) -------------
__device__ float g_x1  [(size_t)MR * Dd];

__device__ __half g_xn_hi [(size_t)MR * Dd];
__device__ __half g_qkv_hi[(size_t)MR * QKVN];
__device__ __half g_at_hi [(size_t)MR * Dd];
__device__ __half g_f1_hi [(size_t)MR * DFFf];
__device__ __half g_wqkv_hi[(size_t)QKVN * Dd];
__device__ __half g_wo_hi[(size_t)Dd * Dd];
__device__ __half g_w1_hi[(size_t)DFFf * Dd];
__device__ __half g_w2_hi[(size_t)Dd * DFFf];
__device__ float g_bqkv[QKVN];

// ---------------- helpers -------------------------------------------------------
__device__ __forceinline__ uint32_t smem_to_u32(const void* p) {
    uint32_t a;
    asm("{ .reg .u64 t; cvta.to.shared.u64 t, %1; cvt.u32.u64 %0, t; }" : "=r"(a) : "l"(p));
    return a;
}
#define SWZ(off) ((off) ^ (((off) >> 3) & 0x70))

#define CP_ASYNC16(dst, src) \
    asm volatile("cp.async.cg.shared.global [%0], [%1], 16;" :: "r"(dst), "l"(src))
#define CP_COMMIT()  asm volatile("cp.async.commit_group;" ::: "memory")
#define CP_WAIT0()   asm volatile("cp.async.wait_group 0;" ::: "memory")
#define CP_WAIT1()   asm volatile("cp.async.wait_group 1;" ::: "memory")

__device__ __forceinline__ void ldsm4(uint32_t& r0, uint32_t& r1, uint32_t& r2, uint32_t& r3,
                                      uint32_t addr) {
    asm volatile("ldmatrix.sync.aligned.m8n8.x4.shared.b16 {%0,%1,%2,%3}, [%4];"
        : "=r"(r0), "=r"(r1), "=r"(r2), "=r"(r3) : "r"(addr));
}
__device__ __forceinline__ void ldsm4t(uint32_t& r0, uint32_t& r1, uint32_t& r2, uint32_t& r3,
                                       uint32_t addr) {
    asm volatile("ldmatrix.sync.aligned.m8n8.x4.trans.shared.b16 {%0,%1,%2,%3}, [%4];"
        : "=r"(r0), "=r"(r1), "=r"(r2), "=r"(r3) : "r"(addr));
}
__device__ __forceinline__ void mma_f16(float* c, const uint32_t* a, const uint32_t* b) {
    asm volatile(
        "mma.sync.aligned.m16n8k16.row.col.f32.f16.f16.f32 "
        "{%0,%1,%2,%3}, {%4,%5,%6,%7}, {%8,%9}, {%0,%1,%2,%3};"
        : "+f"(c[0]), "+f"(c[1]), "+f"(c[2]), "+f"(c[3])
        : "r"(a[0]), "r"(a[1]), "r"(a[2]), "r"(a[3]), "r"(b[0]), "r"(b[1]));
}

__device__ __forceinline__ uint32_t pack_h2(float a, float b) {
    __half ha = __float2half_rn(a), hb = __float2half_rn(b);
    return (uint32_t)__half_as_ushort(ha) | ((uint32_t)__half_as_ushort(hb) << 16);
}

// ---------------- LayerNorm -> fp16, one pass, float4 --------------------------
__global__ void __launch_bounds__(256) ln_kernel(
    const float* __restrict__ x, __half* __restrict__ ohi,
    const float* __restrict__ gamma, const float* __restrict__ beta)
{
    const int row = blockIdx.x;
    const int t = threadIdx.x;
    const float4 v = ((const float4*)(x + (size_t)row * Dd))[t];
    float s  = v.x + v.y + v.z + v.w;
    float sq = v.x * v.x + v.y * v.y + v.z * v.z + v.w * v.w;
    #pragma unroll
    for (int o = 16; o > 0; o >>= 1) {
        s  += __shfl_xor_sync(0xffffffffu, s, o);
        sq += __shfl_xor_sync(0xffffffffu, sq, o);
    }
    __shared__ float rs[8], rq[8];
    __shared__ float bmu, brstd;
    const int w = t >> 5, l = t & 31;
    if (l == 0) { rs[w] = s; rq[w] = sq; }
    __syncthreads();
    if (t == 0) {
        float ts = 0.f, tq = 0.f;
        #pragma unroll
        for (int i = 0; i < 8; i++) { ts += rs[i]; tq += rq[i]; }
        float mu  = ts / (float)Dd;
        float var = (tq - (float)Dd * mu * mu) / (float)(Dd - 1);
        bmu = mu; brstd = rsqrtf(var + 1e-5f);
    }
    __syncthreads();
    const float g = gamma[0], be = beta[0];
    const float mu = bmu, rstd = brstd;
    const float a = g * rstd;
    const float c = be - a * mu;
    ((uint2*)(ohi + (size_t)row * Dd))[t] =
        make_uint2(pack_h2(fmaf(a, v.x, c), fmaf(a, v.y, c)),
                   pack_h2(fmaf(a, v.z, c), fmaf(a, v.w, c)));
}

// ---------------- fused fp32 -> fp16 conversion of ALL weights -----------------
#define SEG (Dd * Dd / 4)   // 256K float4s
__global__ void __launch_bounds__(256) conv_all(
    const float* __restrict__ wq, const float* __restrict__ wk,
    const float* __restrict__ wv, const float* __restrict__ wo,
    const float* __restrict__ w1, const float* __restrict__ w2,
    __half* __restrict__ wqkvh, __half* __restrict__ woh,
    __half* __restrict__ w1h, __half* __restrict__ w2h)
{
    const int gid = blockIdx.x * 256 + threadIdx.x;
    const float* src;
    __half* dst;
    int loc;
    if (gid < 4 * SEG) {
        const int seg = gid >> 18;
        loc = gid & (SEG - 1);
        if (seg == 0)      { src = wq; dst = wqkvh; }
        else if (seg == 1) { src = wk; dst = wqkvh + (size_t)Dd * Dd; }
        else if (seg == 2) { src = wv; dst = wqkvh + (size_t)2 * Dd * Dd; }
        else               { src = wo; dst = woh; }
    } else if (gid < 8 * SEG) {
        src = w1; dst = w1h; loc = gid - 4 * SEG;
    } else {
        src = w2; dst = w2h; loc = gid - 8 * SEG;
    }
    const float4 v = ((const float4*)src)[loc];
    ((uint2*)dst)[loc] = make_uint2(pack_h2(v.x, v.y), pack_h2(v.z, v.w));
}

// ---------------- pack Q/K/V biases into one vector ----------------------------
__global__ void pack_bias(const float* __restrict__ b0, const float* __restrict__ b1,
                          const float* __restrict__ b2, float* __restrict__ dst)
{
    const int i = blockIdx.x * 256 + threadIdx.x;
    if (i < Dd) { dst[i] = b0[i]; dst[Dd + i] = b1[i]; dst[2 * Dd + i] = b2[i]; }
}

// ---------------- fp16 mma GEMM: C = A * W^T -----------------------------------
// CTA tile 128x256, BK=128. 512 threads = 16 warps (4M x 4N), warp tile 32x64.
// 2-stage cp.async pipeline, 96KB/stage. ONE sync per chunk.
// MODE 1: out fp32 = acc + bias + res
// MODE 2: relu(acc + bias) -> fp16
// MODE 3: (acc + bias)     -> fp16
// MODE 4: (acc + bias)     -> fp16, cols < Dd scaled by 0.125 (QKV: fold attn scale into Q)
#define T_A 0
#define T_W 32768
#define STAGE 98304
#define GEMM_SMEM_DYN 196608   // 2 stages

template<int MODE>
__global__ void __launch_bounds__(512) gemm_mma(
    const __half* __restrict__ Ah, const __half* __restrict__ Wh,
    const float* __restrict__ bias, const float* __restrict__ res,
    float* __restrict__ outF, __half* __restrict__ outHi,
    int K, int N)
{
    extern __shared__ char smem[];
    const uint32_t sbase = smem_to_u32(smem);
    const int tid = threadIdx.x, wid = tid >> 5, lane = tid & 31;
    const int rowBase = blockIdx.y * 128, colBase = blockIdx.x * 256;
    const int warpM = wid & 3, warpN = wid >> 2;     // 4x4 warp grid

    float acc[2][8][4];
    #pragma unroll
    for (int mt = 0; mt < 2; mt++)
        #pragma unroll
        for (int nt = 0; nt < 8; nt++)
            #pragma unroll
            for (int r = 0; r < 4; r++) acc[mt][nt][r] = 0.f;

    const int nch = K >> 7;   // BK = 128

    #define PREFETCH(cc, buf) do { \
        const int k0_ = (cc) << 7; \
        const uint32_t sb_ = sbase + (buf) * STAGE; \
        _Pragma("unroll") \
        for (int i_ = 0; i_ < 4; i_++) { \
            const int s_ = tid + 512 * i_; \
            const int sub_ = s_ >> 10; \
            const int r_ = (s_ >> 3) & 127; \
            const int c_ = s_ & 7; \
            const uint32_t sw_ = SWZ((uint32_t)(r_ * 128 + c_ * 16)) + sub_ * 16384; \
            CP_ASYNC16(sb_ + T_A + sw_, Ah + (size_t)(rowBase + r_) * K + k0_ + sub_ * 64 + c_ * 8); \
        } \
        _Pragma("unroll") \
        for (int i_ = 0; i_ < 8; i_++) { \
            const int s_ = tid + 512 * i_; \
            const int sub_ = s_ >> 11; \
            const int r_ = (s_ >> 3) & 255; \
            const int c_ = s_ & 7; \
            const uint32_t sw_ = SWZ((uint32_t)(r_ * 128 + c_ * 16)) + sub_ * 32768; \
            CP_ASYNC16(sb_ + T_W + sw_, Wh + (size_t)(colBase + r_) * K + k0_ + sub_ * 64 + c_ * 8); \
        } \
    } while (0)

    PREFETCH(0, 0); CP_COMMIT();

    for (int c = 0; c < nch; c++) {
        CP_WAIT0();
        __syncthreads();          // loads of chunk c visible; reads of chunk c-1 done
        if (c + 1 < nch) { PREFETCH(c + 1, (c + 1) & 1); CP_COMMIT(); }
        const uint32_t sb = sbase + (c & 1) * STAGE;

        #pragma unroll
        for (int ks = 0; ks < 8; ks++) {
            const uint32_t suboA = (uint32_t)((ks >> 2) * 16384);
            const uint32_t suboW = (uint32_t)((ks >> 2) * 32768);
            const int ksl = ks & 3;
            uint32_t ah[2][4];
            #pragma unroll
            for (int mt = 0; mt < 2; mt++) {
                const int r = warpM * 32 + mt * 16 + (lane & 15);
                const uint32_t off = suboA + SWZ((uint32_t)(r * 128 + ksl * 32 + ((lane >> 4) << 4)));
                ldsm4(ah[mt][0], ah[mt][1], ah[mt][2], ah[mt][3], sb + T_A + off);
            }
            uint32_t bh[8][2];
            #pragma unroll
            for (int ng = 0; ng < 4; ng++) {
                const int r = warpN * 64 + ng * 16 + (lane & 7) + ((lane >> 4) << 3);
                const uint32_t off = suboW + SWZ((uint32_t)(r * 128 + ksl * 32 + (((lane >> 3) & 1) << 4)));
                uint32_t q0, q1, q2, q3;
                ldsm4(q0, q1, q2, q3, sb + T_W + off);
                bh[ng * 2][0] = q0; bh[ng * 2][1] = q1;
                bh[ng * 2 + 1][0] = q2; bh[ng * 2 + 1][1] = q3;
            }
            #pragma unroll
            for (int mt = 0; mt < 2; mt++)
                #pragma unroll
                for (int nt = 0; nt < 8; nt++)
                    mma_f16(acc[mt][nt], ah[mt], bh[nt]);
        }
        __syncthreads();          // reads of chunk c done before buffer reuse at c+2
        // (kept only when another chunk will overwrite this buffer)
        if (c + 2 >= nch && c + 1 < nch) { /* last reuse barrier not needed further */ }
    }

    // epilogue
    #pragma unroll
    for (int mt = 0; mt < 2; mt++) {
        #pragma unroll
        for (int nt = 0; nt < 8; nt++) {
            const int col = colBase + warpN * 64 + nt * 8 + 2 * (lane & 3);
            const int row0 = rowBase + warpM * 32 + mt * 16 + (lane >> 2);
            const float scale = (MODE == 4 && col < Dd) ? 0.125f : 1.f;
            const float bx = bias[col], by = bias[col + 1];
            #pragma unroll
            for (int h = 0; h < 2; h++) {
                const int row = row0 + h * 8;
                float v0 = acc[mt][nt][h * 2]     + bx;
                float v1 = acc[mt][nt][h * 2 + 1] + by;
                if (MODE == 2) {
                    v0 = fmaxf(v0, 0.f); v1 = fmaxf(v1, 0.f);
                    ((uint32_t*)outHi)[((size_t)row * N + col) >> 1] = pack_h2(v0, v1);
                } else if (MODE == 3 || MODE == 4) {
                    ((uint32_t*)outHi)[((size_t)row * N + col) >> 1] =
                        pack_h2(v0 * scale, v1 * scale);
                } else {
                    const float2 rv = *(const float2*)&res[(size_t)row * N + col];
                    float2 o = { v0 + rv.x, v1 + rv.y };
                    *(float2*)&outF[(size_t)row * N + col] = o;
                }
            }
        }
    }
}

// ---------------- Fused flash attention (fp16 mma) -----------------------------
// Q 16KB + 3 KV stages x 32KB {KH,VH} = 112 KB; 2 CTAs/SM pinned.
// Q already carries the 1/sqrt(dk) scale (folded in QKV epilogue MODE 4).
#define SQH 0
#define KV0 16384
#define KVSTG 32768
#define AKH 0
#define AVH 16384
#define ATT_SMEM_DYN 114688

__global__ void __launch_bounds__(256, 2) attn_kernel(
    const __half* __restrict__ QKVh, __half* __restrict__ Oh)
{
    extern __shared__ char smem[];
    const uint32_t sb = smem_to_u32(smem);
    const int tid = threadIdx.x, wid = tid >> 5, lane = tid & 31;
    const int bh = blockIdx.y, b = bh >> 4, h = bh & 15;
    const int q0 = blockIdx.x * 128;
    const size_t qtok = (size_t)b * Ss + q0;
    const int hcol = h * DKk;
    const int qr = wid * 16;

    #define PREFETCH_KV(kt_, buf_) do { \
        const uint32_t kvb_ = sb + KV0 + (buf_) * KVSTG; \
        _Pragma("unroll") \
        for (int i_ = 0; i_ < 4; i_++) { \
            const int s_ = tid + 256 * i_; \
            const int row_ = s_ >> 3, ch_ = s_ & 7; \
            const uint32_t sw_ = SWZ((uint32_t)(row_ * 128 + ch_ * 16)); \
            const size_t gk_ = ((size_t)b * Ss + (kt_) * 128 + row_) * QKVN + Dd + hcol + ch_ * 8; \
            CP_ASYNC16(kvb_ + AKH + sw_, QKVh + gk_); \
            CP_ASYNC16(kvb_ + AVH + sw_, QKVh + gk_ + Dd); \
        } \
    } while (0)

    #pragma unroll
    for (int i = 0; i < 4; i++) {
        const int s = tid + 256 * i;
        const int row = s >> 3, ch = s & 7;
        const uint32_t sw = SWZ((uint32_t)(row * 128 + ch * 16));
        CP_ASYNC16(sb + SQH + sw, QKVh + (qtok + row) * QKVN + hcol + ch * 8);
    }
    PREFETCH_KV(0, 0); CP_COMMIT();
    PREFETCH_KV(1, 1); CP_COMMIT();

    float accO[8][4];
    #pragma unroll
    for (int nt = 0; nt < 8; nt++)
        #pragma unroll
        for (int r = 0; r < 4; r++) accO[nt][r] = 0.f;
    float mrow[2] = { -1e30f, -1e30f };
    float lrow[2] = { 0.f, 0.f };

    int buf = 0;
    for (int kt = 0; kt < 8; kt++) {
        if (kt < 7) CP_WAIT1(); else CP_WAIT0();
        __syncthreads();
        if (kt + 2 < 8) {
            int nb = buf + 2; if (nb >= 3) nb -= 3;
            PREFETCH_KV(kt + 2, nb); CP_COMMIT();
        }
        const uint32_t kvb = sb + KV0 + buf * KVSTG;

        #pragma unroll
        for (int half = 0; half < 2; half++) {
            // ---- S = Q K^T over 64 keys (Q pre-scaled) ----
            float sacc[8][4];
            #pragma unroll
            for (int nt = 0; nt < 8; nt++)
                #pragma unroll
                for (int r = 0; r < 4; r++) sacc[nt][r] = 0.f;

            #pragma unroll
            for (int ks = 0; ks < 4; ks++) {
                uint32_t aqh[4];
                {
                    const int r = qr + (lane & 15);
                    const uint32_t off = SWZ((uint32_t)(r * 128 + ks * 32 + ((lane >> 4) << 4)));
                    ldsm4(aqh[0], aqh[1], aqh[2], aqh[3], sb + SQH + off);
                }
                #pragma unroll
                for (int np = 0; np < 4; np++) {
                    const int r = half * 64 + np * 16 + (lane & 7) + ((lane >> 4) << 3);
                    const uint32_t off = SWZ((uint32_t)(r * 128 + ks * 32 + (((lane >> 3) & 1) << 4)));
                    uint32_t kh0, kh1, kh2, kh3;
                    ldsm4(kh0, kh1, kh2, kh3, kvb + AKH + off);
                    uint32_t bH0[2] = { kh0, kh1 }, bH1[2] = { kh2, kh3 };
                    mma_f16(sacc[np * 2],     aqh, bH0);
                    mma_f16(sacc[np * 2 + 1], aqh, bH1);
                }
            }

            // ---- online softmax ----
            float mx0 = -1e30f, mx1 = -1e30f;
            #pragma unroll
            for (int nt = 0; nt < 8; nt++) {
                mx0 = fmaxf(mx0, fmaxf(sacc[nt][0], sacc[nt][1]));
                mx1 = fmaxf(mx1, fmaxf(sacc[nt][2], sacc[nt][3]));
            }
            mx0 = fmaxf(mx0, __shfl_xor_sync(0xffffffffu, mx0, 1));
            mx0 = fmaxf(mx0, __shfl_xor_sync(0xffffffffu, mx0, 2));
            mx1 = fmaxf(mx1, __shfl_xor_sync(0xffffffffu, mx1, 1));
            mx1 = fmaxf(mx1, __shfl_xor_sync(0xffffffffu, mx1, 2));
            const float nm0 = fmaxf(mrow[0], mx0), nm1 = fmaxf(mrow[1], mx1);
            const float al0 = __expf(mrow[0] - nm0), al1 = __expf(mrow[1] - nm1);
            mrow[0] = nm0; mrow[1] = nm1;
            float sum0 = 0.f, sum1 = 0.f;
            #pragma unroll
            for (int nt = 0; nt < 8; nt++) {
                sacc[nt][0] = __expf(sacc[nt][0] - nm0);
                sacc[nt][1] = __expf(sacc[nt][1] - nm0);
                sacc[nt][2] = __expf(sacc[nt][2] - nm1);
                sacc[nt][3] = __expf(sacc[nt][3] - nm1);
                sum0 += sacc[nt][0] + sacc[nt][1];
                sum1 += sacc[nt][2] + sacc[nt][3];
                accO[nt][0] *= al0; accO[nt][1] *= al0;
                accO[nt][2] *= al1; accO[nt][3] *= al1;
            }
            sum0 += __shfl_xor_sync(0xffffffffu, sum0, 1);
            sum0 += __shfl_xor_sync(0xffffffffu, sum0, 2);
            sum1 += __shfl_xor_sync(0xffffffffu, sum1, 1);
            sum1 += __shfl_xor_sync(0xffffffffu, sum1, 2);
            lrow[0] = lrow[0] * al0 + sum0;
            lrow[1] = lrow[1] * al1 + sum1;

            // ---- O += P V ----
            #pragma unroll
            for (int t = 0; t < 4; t++) {
                uint32_t pah[4];
                pah[0] = pack_h2(sacc[2 * t][0],     sacc[2 * t][1]);
                pah[1] = pack_h2(sacc[2 * t][2],     sacc[2 * t][3]);
                pah[2] = pack_h2(sacc[2 * t + 1][0], sacc[2 * t + 1][1]);
                pah[3] = pack_h2(sacc[2 * t + 1][2], sacc[2 * t + 1][3]);
                const int k0 = half * 64 + t * 16;
                #pragma unroll
                for (int np = 0; np < 4; np++) {
                    const int krow = k0 + (lane & 15);
                    const int col = np * 16 + ((lane >> 4) << 3);
                    const uint32_t off = SWZ((uint32_t)(krow * 128 + col * 2));
                    uint32_t vh0, vh1, vh2, vh3;
                    ldsm4t(vh0, vh1, vh2, vh3, kvb + AVH + off);
                    uint32_t bH0[2] = { vh0, vh1 }, bH1[2] = { vh2, vh3 };
                    mma_f16(accO[np * 2],     pah, bH0);
                    mma_f16(accO[np * 2 + 1], pah, bH1);
                }
            }
        }
        buf++; if (buf >= 3) buf = 0;
    }

    // ---- epilogue: O / l -> fp16 gmem (stride Dd) ----
    const float inv0 = 1.f / lrow[0], inv1 = 1.f / lrow[1];
    #pragma unroll
    for (int nt = 0; nt < 8; nt++) {
        const int col = hcol + nt * 8 + 2 * (lane & 3);
        #pragma unroll
        for (int g = 0; g < 2; g++) {
            const size_t tok = qtok + qr + (lane >> 2) + g * 8;
            const float inv = g ? inv1 : inv0;
            ((uint32_t*)Oh)[(tok * Dd + col) >> 1] =
                pack_h2(accO[nt][2 * g] * inv, accO[nt][2 * g + 1] * inv);
        }
    }
}

// ---------------- launch --------------------------------------------------------
extern "C" void kernel_launch(void* const* d_in, const int* in_sizes, int n_in,
                              void* d_out, int out_size)
{
    const float* x   = (const float*)d_in[0];
    const float* wq  = (const float*)d_in[2];
    const float* bq  = (const float*)d_in[3];
    const float* wk  = (const float*)d_in[4];
    const float* bk  = (const float*)d_in[5];
    const float* wv  = (const float*)d_in[6];
    const float* bv  = (const float*)d_in[7];
    const float* wo  = (const float*)d_in[8];
    const float* bo  = (const float*)d_in[9];
    const float* w1  = (const float*)d_in[10];
    const float* b1  = (const float*)d_in[11];
    const float* w2  = (const float*)d_in[12];
    const float* b2  = (const float*)d_in[13];
    const float* g1  = (const float*)d_in[14];
    const float* be1 = (const float*)d_in[15];
    const float* g2  = (const float*)d_in[16];
    const float* be2 = (const float*)d_in[17];
    float* out = (float*)d_out;

    float *x1, *bqkv;
    __half *xnh, *qkvh, *ath, *f1h, *wqkvh, *woh, *w1h, *w2h;
    cudaGetSymbolAddress((void**)&x1,    g_x1);
    cudaGetSymbolAddress((void**)&bqkv,  g_bqkv);
    cudaGetSymbolAddress((void**)&xnh,   g_xn_hi);
    cudaGetSymbolAddress((void**)&qkvh,  g_qkv_hi);
    cudaGetSymbolAddress((void**)&ath,   g_at_hi);
    cudaGetSymbolAddress((void**)&f1h,   g_f1_hi);
    cudaGetSymbolAddress((void**)&wqkvh, g_wqkv_hi);
    cudaGetSymbolAddress((void**)&woh,   g_wo_hi);
    cudaGetSymbolAddress((void**)&w1h,   g_w1_hi);
    cudaGetSymbolAddress((void**)&w2h,   g_w2_hi);

    cudaFuncSetAttribute(gemm_mma<1>, cudaFuncAttributeMaxDynamicSharedMemorySize, GEMM_SMEM_DYN);
    cudaFuncSetAttribute(gemm_mma<2>, cudaFuncAttributeMaxDynamicSharedMemorySize, GEMM_SMEM_DYN);
    cudaFuncSetAttribute(gemm_mma<4>, cudaFuncAttributeMaxDynamicSharedMemorySize, GEMM_SMEM_DYN);
    cudaFuncSetAttribute(attn_kernel, cudaFuncAttributeMaxDynamicSharedMemorySize, ATT_SMEM_DYN);

    // all weight conversions in one launch (12M floats = 3M float4s)
    conv_all<<<(12 * SEG) / 256, 256>>>(wq, wk, wv, wo, w1, w2, wqkvh, woh, w1h, w2h);
    pack_bias<<<Dd / 256, 256>>>(bq, bk, bv, bqkv);

    // LN1 -> fp16
    ln_kernel<<<MR, 256>>>(x, xnh, g1, be1);

    // fused QKV projection -> packed fp16 [MR x 3072], Q pre-scaled by 1/8
    gemm_mma<4><<<dim3(QKVN/256, MR/128), 512, GEMM_SMEM_DYN>>>(
        xnh, wqkvh, bqkv, nullptr, nullptr, qkvh, Dd, QKVN);

    // fused flash attention -> fp16
    attn_kernel<<<dim3(Ss/128, Bb*Hh), 256, ATT_SMEM_DYN>>>(qkvh, ath);

    // output projection + residual (fp32)
    gemm_mma<1><<<dim3(Dd/256, MR/128), 512, GEMM_SMEM_DYN>>>(
        ath, woh, bo, x, x1, nullptr, Dd, Dd);

    // LN2 -> fp16
    ln_kernel<<<MR, 256>>>(x1, xnh, g2, be2);

    // FFN
    gemm_mma<2><<<dim3(DFFf/256, MR/128), 512, GEMM_SMEM_DYN>>>(
        xnh, w1h, b1, nullptr, nullptr, f1h, Dd, DFFf);
    gemm_mma<1><<<dim3(Dd/256, MR/128), 512, GEMM_SMEM_DYN>>>(
        f1h, w2h, b2, x1, out, nullptr, DFFf, Dd);
}

// round 16
// speedup vs baseline: 1.5505x; 1.0156x over previous
#include <cuda_runtime.h>
#include <cuda_fp16.h>
#include <cstdint>

// Problem dims
#define Bb   8
#define Ss   1024
#define Dd   1024
#define Hh   16
#define DKk  64
#define DFFf 4096
#define MR   (Bb * Ss)   // 8192 rows
#define QKVN 3072

// ---------------- scratch (device globals; no allocations allowed) -------------
__device__ float g_x1  [(size_t)MR * Dd];

__device__ __half g_xn_hi [(size_t)MR * Dd];
__device__ __half g_qkv_hi[(size_t)MR * QKVN];
__device__ __half g_at_hi [(size_t)MR * Dd];
__device__ __half g_f1_hi [(size_t)MR * DFFf];
__device__ __half g_wqkv_hi[(size_t)QKVN * Dd];
__device__ __half g_wo_hi[(size_t)Dd * Dd];
__device__ __half g_w1_hi[(size_t)DFFf * Dd];
__device__ __half g_w2_hi[(size_t)Dd * DFFf];
__device__ float g_bqkv[QKVN];

// ---------------- helpers -------------------------------------------------------
__device__ __forceinline__ uint32_t smem_to_u32(const void* p) {
    uint32_t a;
    asm("{ .reg .u64 t; cvta.to.shared.u64 t, %1; cvt.u32.u64 %0, t; }" : "=r"(a) : "l"(p));
    return a;
}
#define SWZ(off) ((off) ^ (((off) >> 3) & 0x70))

#define CP_ASYNC16(dst, src) \
    asm volatile("cp.async.cg.shared.global [%0], [%1], 16;" :: "r"(dst), "l"(src))
#define CP_COMMIT()  asm volatile("cp.async.commit_group;" ::: "memory")
#define CP_WAIT0()   asm volatile("cp.async.wait_group 0;" ::: "memory")
#define CP_WAIT1()   asm volatile("cp.async.wait_group 1;" ::: "memory")

__device__ __forceinline__ void ldsm4(uint32_t& r0, uint32_t& r1, uint32_t& r2, uint32_t& r3,
                                      uint32_t addr) {
    asm volatile("ldmatrix.sync.aligned.m8n8.x4.shared.b16 {%0,%1,%2,%3}, [%4];"
        : "=r"(r0), "=r"(r1), "=r"(r2), "=r"(r3) : "r"(addr));
}
__device__ __forceinline__ void ldsm4t(uint32_t& r0, uint32_t& r1, uint32_t& r2, uint32_t& r3,
                                       uint32_t addr) {
    asm volatile("ldmatrix.sync.aligned.m8n8.x4.trans.shared.b16 {%0,%1,%2,%3}, [%4];"
        : "=r"(r0), "=r"(r1), "=r"(r2), "=r"(r3) : "r"(addr));
}
__device__ __forceinline__ void mma_f16(float* c, const uint32_t* a, const uint32_t* b) {
    asm volatile(
        "mma.sync.aligned.m16n8k16.row.col.f32.f16.f16.f32 "
        "{%0,%1,%2,%3}, {%4,%5,%6,%7}, {%8,%9}, {%0,%1,%2,%3};"
        : "+f"(c[0]), "+f"(c[1]), "+f"(c[2]), "+f"(c[3])
        : "r"(a[0]), "r"(a[1]), "r"(a[2]), "r"(a[3]), "r"(b[0]), "r"(b[1]));
}

__device__ __forceinline__ uint32_t pack_h2(float a, float b) {
    __half ha = __float2half_rn(a), hb = __float2half_rn(b);
    return (uint32_t)__half_as_ushort(ha) | ((uint32_t)__half_as_ushort(hb) << 16);
}

// ---------------- LayerNorm -> fp16, one pass, float4 --------------------------
__global__ void __launch_bounds__(256) ln_kernel(
    const float* __restrict__ x, __half* __restrict__ ohi,
    const float* __restrict__ gamma, const float* __restrict__ beta)
{
    const int row = blockIdx.x;
    const int t = threadIdx.x;
    const float4 v = ((const float4*)(x + (size_t)row * Dd))[t];
    float s  = v.x + v.y + v.z + v.w;
    float sq = v.x * v.x + v.y * v.y + v.z * v.z + v.w * v.w;
    #pragma unroll
    for (int o = 16; o > 0; o >>= 1) {
        s  += __shfl_xor_sync(0xffffffffu, s, o);
        sq += __shfl_xor_sync(0xffffffffu, sq, o);
    }
    __shared__ float rs[8], rq[8];
    __shared__ float bmu, brstd;
    const int w = t >> 5, l = t & 31;
    if (l == 0) { rs[w] = s; rq[w] = sq; }
    __syncthreads();
    if (t == 0) {
        float ts = 0.f, tq = 0.f;
        #pragma unroll
        for (int i = 0; i < 8; i++) { ts += rs[i]; tq += rq[i]; }
        float mu  = ts / (float)Dd;
        float var = (tq - (float)Dd * mu * mu) / (float)(Dd - 1);
        bmu = mu; brstd = rsqrtf(var + 1e-5f);
    }
    __syncthreads();
    const float g = gamma[0], be = beta[0];
    const float mu = bmu, rstd = brstd;
    const float a = g * rstd;
    const float c = be - a * mu;
    ((uint2*)(ohi + (size_t)row * Dd))[t] =
        make_uint2(pack_h2(fmaf(a, v.x, c), fmaf(a, v.y, c)),
                   pack_h2(fmaf(a, v.z, c), fmaf(a, v.w, c)));
}

// ---------------- fused fp32 -> fp16 conversion of ALL weights -----------------
#define SEG (Dd * Dd / 4)   // 256K float4s
__global__ void __launch_bounds__(256) conv_all(
    const float* __restrict__ wq, const float* __restrict__ wk,
    const float* __restrict__ wv, const float* __restrict__ wo,
    const float* __restrict__ w1, const float* __restrict__ w2,
    __half* __restrict__ wqkvh, __half* __restrict__ woh,
    __half* __restrict__ w1h, __half* __restrict__ w2h)
{
    const int gid = blockIdx.x * 256 + threadIdx.x;
    const float* src;
    __half* dst;
    int loc;
    if (gid < 4 * SEG) {
        const int seg = gid >> 18;
        loc = gid & (SEG - 1);
        if (seg == 0)      { src = wq; dst = wqkvh; }
        else if (seg == 1) { src = wk; dst = wqkvh + (size_t)Dd * Dd; }
        else if (seg == 2) { src = wv; dst = wqkvh + (size_t)2 * Dd * Dd; }
        else               { src = wo; dst = woh; }
    } else if (gid < 8 * SEG) {
        src = w1; dst = w1h; loc = gid - 4 * SEG;
    } else {
        src = w2; dst = w2h; loc = gid - 8 * SEG;
    }
    const float4 v = ((const float4*)src)[loc];
    ((uint2*)dst)[loc] = make_uint2(pack_h2(v.x, v.y), pack_h2(v.z, v.w));
}

// ---------------- pack Q/K/V biases into one vector ----------------------------
__global__ void pack_bias(const float* __restrict__ b0, const float* __restrict__ b1,
                          const float* __restrict__ b2, float* __restrict__ dst)
{
    const int i = blockIdx.x * 256 + threadIdx.x;
    if (i < Dd) { dst[i] = b0[i]; dst[Dd + i] = b1[i]; dst[2 * Dd + i] = b2[i]; }
}

// ---------------- fp16 mma GEMM: C = A * W^T -----------------------------------
// CTA tile 128x256, BK=128. 512 threads = 16 warps (4M x 4N), warp tile 32x64.
// 2-stage cp.async pipeline, 96KB/stage. ONE __syncthreads per chunk:
//   prefetch at iter c targets buffer (c+1)&1, last read at iter c-1; those reads
//   precede each thread's arrival at the top barrier of iter c, so the top
//   barrier alone orders buffer reuse.
// MODE 1: out fp32 = acc + bias + res
// MODE 2: relu(acc + bias) -> fp16
// MODE 4: (acc + bias)     -> fp16, cols < Dd scaled by 0.125 (QKV: fold attn scale)
#define T_A 0
#define T_W 32768
#define STAGE 98304
#define GEMM_SMEM_DYN 196608   // 2 stages

template<int MODE>
__global__ void __launch_bounds__(512) gemm_mma(
    const __half* __restrict__ Ah, const __half* __restrict__ Wh,
    const float* __restrict__ bias, const float* __restrict__ res,
    float* __restrict__ outF, __half* __restrict__ outHi,
    int K, int N)
{
    extern __shared__ char smem[];
    const uint32_t sbase = smem_to_u32(smem);
    const int tid = threadIdx.x, wid = tid >> 5, lane = tid & 31;
    const int rowBase = blockIdx.y * 128, colBase = blockIdx.x * 256;
    const int warpM = wid & 3, warpN = wid >> 2;     // 4x4 warp grid

    float acc[2][8][4];
    #pragma unroll
    for (int mt = 0; mt < 2; mt++)
        #pragma unroll
        for (int nt = 0; nt < 8; nt++)
            #pragma unroll
            for (int r = 0; r < 4; r++) acc[mt][nt][r] = 0.f;

    const int nch = K >> 7;   // BK = 128

    #define PREFETCH(cc, buf) do { \
        const int k0_ = (cc) << 7; \
        const uint32_t sb_ = sbase + (buf) * STAGE; \
        _Pragma("unroll") \
        for (int i_ = 0; i_ < 4; i_++) { \
            const int s_ = tid + 512 * i_; \
            const int sub_ = s_ >> 10; \
            const int r_ = (s_ >> 3) & 127; \
            const int c_ = s_ & 7; \
            const uint32_t sw_ = SWZ((uint32_t)(r_ * 128 + c_ * 16)) + sub_ * 16384; \
            CP_ASYNC16(sb_ + T_A + sw_, Ah + (size_t)(rowBase + r_) * K + k0_ + sub_ * 64 + c_ * 8); \
        } \
        _Pragma("unroll") \
        for (int i_ = 0; i_ < 8; i_++) { \
            const int s_ = tid + 512 * i_; \
            const int sub_ = s_ >> 11; \
            const int r_ = (s_ >> 3) & 255; \
            const int c_ = s_ & 7; \
            const uint32_t sw_ = SWZ((uint32_t)(r_ * 128 + c_ * 16)) + sub_ * 32768; \
            CP_ASYNC16(sb_ + T_W + sw_, Wh + (size_t)(colBase + r_) * K + k0_ + sub_ * 64 + c_ * 8); \
        } \
    } while (0)

    PREFETCH(0, 0); CP_COMMIT();

    for (int c = 0; c < nch; c++) {
        CP_WAIT0();
        __syncthreads();     // single barrier: chunk c visible AND buffer (c+1)&1 free
        if (c + 1 < nch) { PREFETCH(c + 1, (c + 1) & 1); CP_COMMIT(); }
        const uint32_t sb = sbase + (c & 1) * STAGE;

        #pragma unroll
        for (int ks = 0; ks < 8; ks++) {
            const uint32_t suboA = (uint32_t)((ks >> 2) * 16384);
            const uint32_t suboW = (uint32_t)((ks >> 2) * 32768);
            const int ksl = ks & 3;
            uint32_t ah[2][4];
            #pragma unroll
            for (int mt = 0; mt < 2; mt++) {
                const int r = warpM * 32 + mt * 16 + (lane & 15);
                const uint32_t off = suboA + SWZ((uint32_t)(r * 128 + ksl * 32 + ((lane >> 4) << 4)));
                ldsm4(ah[mt][0], ah[mt][1], ah[mt][2], ah[mt][3], sb + T_A + off);
            }
            uint32_t bh[8][2];
            #pragma unroll
            for (int ng = 0; ng < 4; ng++) {
                const int r = warpN * 64 + ng * 16 + (lane & 7) + ((lane >> 4) << 3);
                const uint32_t off = suboW + SWZ((uint32_t)(r * 128 + ksl * 32 + (((lane >> 3) & 1) << 4)));
                uint32_t q0, q1, q2, q3;
                ldsm4(q0, q1, q2, q3, sb + T_W + off);
                bh[ng * 2][0] = q0; bh[ng * 2][1] = q1;
                bh[ng * 2 + 1][0] = q2; bh[ng * 2 + 1][1] = q3;
            }
            #pragma unroll
            for (int mt = 0; mt < 2; mt++)
                #pragma unroll
                for (int nt = 0; nt < 8; nt++)
                    mma_f16(acc[mt][nt], ah[mt], bh[nt]);
        }
        // no bottom barrier (see header comment)
    }

    // epilogue
    #pragma unroll
    for (int mt = 0; mt < 2; mt++) {
        #pragma unroll
        for (int nt = 0; nt < 8; nt++) {
            const int col = colBase + warpN * 64 + nt * 8 + 2 * (lane & 3);
            const int row0 = rowBase + warpM * 32 + mt * 16 + (lane >> 2);
            const float scale = (MODE == 4 && col < Dd) ? 0.125f : 1.f;
            const float bx = bias[col], by = bias[col + 1];
            #pragma unroll
            for (int h = 0; h < 2; h++) {
                const int row = row0 + h * 8;
                float v0 = acc[mt][nt][h * 2]     + bx;
                float v1 = acc[mt][nt][h * 2 + 1] + by;
                if (MODE == 2) {
                    v0 = fmaxf(v0, 0.f); v1 = fmaxf(v1, 0.f);
                    ((uint32_t*)outHi)[((size_t)row * N + col) >> 1] = pack_h2(v0, v1);
                } else if (MODE == 4) {
                    ((uint32_t*)outHi)[((size_t)row * N + col) >> 1] =
                        pack_h2(v0 * scale, v1 * scale);
                } else {
                    const float2 rv = *(const float2*)&res[(size_t)row * N + col];
                    float2 o = { v0 + rv.x, v1 + rv.y };
                    *(float2*)&outF[(size_t)row * N + col] = o;
                }
            }
        }
    }
}

// ---------------- Fused flash attention (fp16 mma) -----------------------------
// Q 16KB + 3 KV stages x 32KB {KH,VH} = 112 KB; 2 CTAs/SM pinned.
// Q already carries the 1/sqrt(dk) scale (folded in QKV epilogue MODE 4).
#define SQH 0
#define KV0 16384
#define KVSTG 32768
#define AKH 0
#define AVH 16384
#define ATT_SMEM_DYN 114688

__global__ void __launch_bounds__(256, 2) attn_kernel(
    const __half* __restrict__ QKVh, __half* __restrict__ Oh)
{
    extern __shared__ char smem[];
    const uint32_t sb = smem_to_u32(smem);
    const int tid = threadIdx.x, wid = tid >> 5, lane = tid & 31;
    const int bh = blockIdx.y, b = bh >> 4, h = bh & 15;
    const int q0 = blockIdx.x * 128;
    const size_t qtok = (size_t)b * Ss + q0;
    const int hcol = h * DKk;
    const int qr = wid * 16;

    #define PREFETCH_KV(kt_, buf_) do { \
        const uint32_t kvb_ = sb + KV0 + (buf_) * KVSTG; \
        _Pragma("unroll") \
        for (int i_ = 0; i_ < 4; i_++) { \
            const int s_ = tid + 256 * i_; \
            const int row_ = s_ >> 3, ch_ = s_ & 7; \
            const uint32_t sw_ = SWZ((uint32_t)(row_ * 128 + ch_ * 16)); \
            const size_t gk_ = ((size_t)b * Ss + (kt_) * 128 + row_) * QKVN + Dd + hcol + ch_ * 8; \
            CP_ASYNC16(kvb_ + AKH + sw_, QKVh + gk_); \
            CP_ASYNC16(kvb_ + AVH + sw_, QKVh + gk_ + Dd); \
        } \
    } while (0)

    #pragma unroll
    for (int i = 0; i < 4; i++) {
        const int s = tid + 256 * i;
        const int row = s >> 3, ch = s & 7;
        const uint32_t sw = SWZ((uint32_t)(row * 128 + ch * 16));
        CP_ASYNC16(sb + SQH + sw, QKVh + (qtok + row) * QKVN + hcol + ch * 8);
    }
    PREFETCH_KV(0, 0); CP_COMMIT();
    PREFETCH_KV(1, 1); CP_COMMIT();

    float accO[8][4];
    #pragma unroll
    for (int nt = 0; nt < 8; nt++)
        #pragma unroll
        for (int r = 0; r < 4; r++) accO[nt][r] = 0.f;
    float mrow[2] = { -1e30f, -1e30f };
    float lrow[2] = { 0.f, 0.f };

    int buf = 0;
    for (int kt = 0; kt < 8; kt++) {
        if (kt < 7) CP_WAIT1(); else CP_WAIT0();
        __syncthreads();
        if (kt + 2 < 8) {
            int nb = buf + 2; if (nb >= 3) nb -= 3;
            PREFETCH_KV(kt + 2, nb); CP_COMMIT();
        }
        const uint32_t kvb = sb + KV0 + buf * KVSTG;

        #pragma unroll
        for (int half = 0; half < 2; half++) {
            // ---- S = Q K^T over 64 keys (Q pre-scaled) ----
            float sacc[8][4];
            #pragma unroll
            for (int nt = 0; nt < 8; nt++)
                #pragma unroll
                for (int r = 0; r < 4; r++) sacc[nt][r] = 0.f;

            #pragma unroll
            for (int ks = 0; ks < 4; ks++) {
                uint32_t aqh[4];
                {
                    const int r = qr + (lane & 15);
                    const uint32_t off = SWZ((uint32_t)(r * 128 + ks * 32 + ((lane >> 4) << 4)));
                    ldsm4(aqh[0], aqh[1], aqh[2], aqh[3], sb + SQH + off);
                }
                #pragma unroll
                for (int np = 0; np < 4; np++) {
                    const int r = half * 64 + np * 16 + (lane & 7) + ((lane >> 4) << 3);
                    const uint32_t off = SWZ((uint32_t)(r * 128 + ks * 32 + (((lane >> 3) & 1) << 4)));
                    uint32_t kh0, kh1, kh2, kh3;
                    ldsm4(kh0, kh1, kh2, kh3, kvb + AKH + off);
                    uint32_t bH0[2] = { kh0, kh1 }, bH1[2] = { kh2, kh3 };
                    mma_f16(sacc[np * 2],     aqh, bH0);
                    mma_f16(sacc[np * 2 + 1], aqh, bH1);
                }
            }

            // ---- online softmax ----
            float mx0 = -1e30f, mx1 = -1e30f;
            #pragma unroll
            for (int nt = 0; nt < 8; nt++) {
                mx0 = fmaxf(mx0, fmaxf(sacc[nt][0], sacc[nt][1]));
                mx1 = fmaxf(mx1, fmaxf(sacc[nt][2], sacc[nt][3]));
            }
            mx0 = fmaxf(mx0, __shfl_xor_sync(0xffffffffu, mx0, 1));
            mx0 = fmaxf(mx0, __shfl_xor_sync(0xffffffffu, mx0, 2));
            mx1 = fmaxf(mx1, __shfl_xor_sync(0xffffffffu, mx1, 1));
            mx1 = fmaxf(mx1, __shfl_xor_sync(0xffffffffu, mx1, 2));
            const float nm0 = fmaxf(mrow[0], mx0), nm1 = fmaxf(mrow[1], mx1);
            const float al0 = __expf(mrow[0] - nm0), al1 = __expf(mrow[1] - nm1);
            mrow[0] = nm0; mrow[1] = nm1;
            float sum0 = 0.f, sum1 = 0.f;
            #pragma unroll
            for (int nt = 0; nt < 8; nt++) {
                sacc[nt][0] = __expf(sacc[nt][0] - nm0);
                sacc[nt][1] = __expf(sacc[nt][1] - nm0);
                sacc[nt][2] = __expf(sacc[nt][2] - nm1);
                sacc[nt][3] = __expf(sacc[nt][3] - nm1);
                sum0 += sacc[nt][0] + sacc[nt][1];
                sum1 += sacc[nt][2] + sacc[nt][3];
                accO[nt][0] *= al0; accO[nt][1] *= al0;
                accO[nt][2] *= al1; accO[nt][3] *= al1;
            }
            sum0 += __shfl_xor_sync(0xffffffffu, sum0, 1);
            sum0 += __shfl_xor_sync(0xffffffffu, sum0, 2);
            sum1 += __shfl_xor_sync(0xffffffffu, sum1, 1);
            sum1 += __shfl_xor_sync(0xffffffffu, sum1, 2);
            lrow[0] = lrow[0] * al0 + sum0;
            lrow[1] = lrow[1] * al1 + sum1;

            // ---- O += P V ----
            #pragma unroll
            for (int t = 0; t < 4; t++) {
                uint32_t pah[4];
                pah[0] = pack_h2(sacc[2 * t][0],     sacc[2 * t][1]);
                pah[1] = pack_h2(sacc[2 * t][2],     sacc[2 * t][3]);
                pah[2] = pack_h2(sacc[2 * t + 1][0], sacc[2 * t + 1][1]);
                pah[3] = pack_h2(sacc[2 * t + 1][2], sacc[2 * t + 1][3]);
                const int k0 = half * 64 + t * 16;
                #pragma unroll
                for (int np = 0; np < 4; np++) {
                    const int krow = k0 + (lane & 15);
                    const int col = np * 16 + ((lane >> 4) << 3);
                    const uint32_t off = SWZ((uint32_t)(krow * 128 + col * 2));
                    uint32_t vh0, vh1, vh2, vh3;
                    ldsm4t(vh0, vh1, vh2, vh3, kvb + AVH + off);
                    uint32_t bH0[2] = { vh0, vh1 }, bH1[2] = { vh2, vh3 };
                    mma_f16(accO[np * 2],     pah, bH0);
                    mma_f16(accO[np * 2 + 1], pah, bH1);
                }
            }
        }
        buf++; if (buf >= 3) buf = 0;
    }

    // ---- epilogue: O / l -> fp16 gmem (stride Dd) ----
    const float inv0 = 1.f / lrow[0], inv1 = 1.f / lrow[1];
    #pragma unroll
    for (int nt = 0; nt < 8; nt++) {
        const int col = hcol + nt * 8 + 2 * (lane & 3);
        #pragma unroll
        for (int g = 0; g < 2; g++) {
            const size_t tok = qtok + qr + (lane >> 2) + g * 8;
            const float inv = g ? inv1 : inv0;
            ((uint32_t*)Oh)[(tok * Dd + col) >> 1] =
                pack_h2(accO[nt][2 * g] * inv, accO[nt][2 * g + 1] * inv);
        }
    }
}

// ---------------- launch --------------------------------------------------------
extern "C" void kernel_launch(void* const* d_in, const int* in_sizes, int n_in,
                              void* d_out, int out_size)
{
    const float* x   = (const float*)d_in[0];
    const float* wq  = (const float*)d_in[2];
    const float* bq  = (const float*)d_in[3];
    const float* wk  = (const float*)d_in[4];
    const float* bk  = (const float*)d_in[5];
    const float* wv  = (const float*)d_in[6];
    const float* bv  = (const float*)d_in[7];
    const float* wo  = (const float*)d_in[8];
    const float* bo  = (const float*)d_in[9];
    const float* w1  = (const float*)d_in[10];
    const float* b1  = (const float*)d_in[11];
    const float* w2  = (const float*)d_in[12];
    const float* b2  = (const float*)d_in[13];
    const float* g1  = (const float*)d_in[14];
    const float* be1 = (const float*)d_in[15];
    const float* g2  = (const float*)d_in[16];
    const float* be2 = (const float*)d_in[17];
    float* out = (float*)d_out;

    float *x1, *bqkv;
    __half *xnh, *qkvh, *ath, *f1h, *wqkvh, *woh, *w1h, *w2h;
    cudaGetSymbolAddress((void**)&x1,    g_x1);
    cudaGetSymbolAddress((void**)&bqkv,  g_bqkv);
    cudaGetSymbolAddress((void**)&xnh,   g_xn_hi);
    cudaGetSymbolAddress((void**)&qkvh,  g_qkv_hi);
    cudaGetSymbolAddress((void**)&ath,   g_at_hi);
    cudaGetSymbolAddress((void**)&f1h,   g_f1_hi);
    cudaGetSymbolAddress((void**)&wqkvh, g_wqkv_hi);
    cudaGetSymbolAddress((void**)&woh,   g_wo_hi);
    cudaGetSymbolAddress((void**)&w1h,   g_w1_hi);
    cudaGetSymbolAddress((void**)&w2h,   g_w2_hi);

    cudaFuncSetAttribute(gemm_mma<1>, cudaFuncAttributeMaxDynamicSharedMemorySize, GEMM_SMEM_DYN);
    cudaFuncSetAttribute(gemm_mma<2>, cudaFuncAttributeMaxDynamicSharedMemorySize, GEMM_SMEM_DYN);
    cudaFuncSetAttribute(gemm_mma<4>, cudaFuncAttributeMaxDynamicSharedMemorySize, GEMM_SMEM_DYN);
    cudaFuncSetAttribute(attn_kernel, cudaFuncAttributeMaxDynamicSharedMemorySize, ATT_SMEM_DYN);

    // all weight conversions in one launch (12M floats = 3M float4s)
    conv_all<<<(12 * SEG) / 256, 256>>>(wq, wk, wv, wo, w1, w2, wqkvh, woh, w1h, w2h);
    pack_bias<<<Dd / 256, 256>>>(bq, bk, bv, bqkv);

    // LN1 -> fp16
    ln_kernel<<<MR, 256>>>(x, xnh, g1, be1);

    // fused QKV projection -> packed fp16 [MR x 3072], Q pre-scaled by 1/8
    gemm_mma<4><<<dim3(QKVN/256, MR/128), 512, GEMM_SMEM_DYN>>>(
        xnh, wqkvh, bqkv, nullptr, nullptr, qkvh, Dd, QKVN);

    // fused flash attention -> fp16
    attn_kernel<<<dim3(Ss/128, Bb*Hh), 256, ATT_SMEM_DYN>>>(qkvh, ath);

    // output projection + residual (fp32)
    gemm_mma<1><<<dim3(Dd/256, MR/128), 512, GEMM_SMEM_DYN>>>(
        ath, woh, bo, x, x1, nullptr, Dd, Dd);

    // LN2 -> fp16
    ln_kernel<<<MR, 256>>>(x1, xnh, g2, be2);

    // FFN
    gemm_mma<2><<<dim3(DFFf/256, MR/128), 512, GEMM_SMEM_DYN>>>(
        xnh, w1h, b1, nullptr, nullptr, f1h, Dd, DFFf);
    gemm_mma<1><<<dim3(Dd/256, MR/128), 512, GEMM_SMEM_DYN>>>(
        f1h, w2h, b2, x1, out, nullptr, DFFf, Dd);
}